// round 13
// baseline (speedup 1.0000x reference)
#include <cuda_runtime.h>
#include <cuda_fp16.h>
#include <math.h>

#define BB   16
#define WWC  64
#define TT   20
#define YHN  33
#define NF   2112          // 64 * 33
#define BWN  1024          // BB * WWC
#define TILE 4096
#define LDH  72            // H smem row stride in halfs (144B, bank-rotating)
#define LDW  72            // W smem row stride in halfs
#define WFS  8192          // halfs per f per gate in GLOBAL (compact): 2*64*64

typedef unsigned int u32;

// ---------------- device scratch ------------------------------------------
static __device__ float  d_h [BWN*TILE];
static __device__ __align__(16) __half2 d_A1 [(size_t)BWN*YHN*64];   // [bw][k][x]
static __device__ __align__(16) __half2 d_Hf [(size_t)NF*BWN];       // [f][bw]
static __device__ __align__(16) __half2 d_F0 [(size_t)NF*BWN];
static __device__ __align__(16) __half2 d_F1 [(size_t)NF*BWN];
static __device__ __align__(16) __half2 d_Ax0[(size_t)BWN*YHN*64];   // [bw][k][x]
static __device__ __align__(16) __half2 d_Ax1[(size_t)BWN*YHN*64];
static __device__ __align__(16) __half  d_Wt [3][(size_t)NF*WFS];    // [f][p][w][o] compact

// ---------------- PDL helpers -------------------------------------------------
__device__ __forceinline__ void pdl_wait()    { asm volatile("griddepcontrol.wait;" ::: "memory"); }
__device__ __forceinline__ void pdl_trigger() { asm volatile("griddepcontrol.launch_dependents;" ::: "memory"); }

// ---------------- mma / ldmatrix helpers -------------------------------------
__device__ __forceinline__ u32 smem_u32(const void* p) {
    return (u32)__cvta_generic_to_shared(p);
}
__device__ __forceinline__ void ldsm_x4(u32& r0, u32& r1, u32& r2,
                                        u32& r3, u32 addr) {
    asm volatile("ldmatrix.sync.aligned.m8n8.x4.shared.b16 {%0,%1,%2,%3},[%4];"
                 : "=r"(r0), "=r"(r1), "=r"(r2), "=r"(r3) : "r"(addr));
}
__device__ __forceinline__ void ldsm_x4t(u32& r0, u32& r1, u32& r2,
                                         u32& r3, u32 addr) {
    asm volatile("ldmatrix.sync.aligned.m8n8.x4.trans.shared.b16 {%0,%1,%2,%3},[%4];"
                 : "=r"(r0), "=r"(r1), "=r"(r2), "=r"(r3) : "r"(addr));
}
__device__ __forceinline__ void mma16816(float* c, const u32* a,
                                         u32 b0, u32 b1) {
    asm volatile(
        "mma.sync.aligned.m16n8k16.row.col.f32.f16.f16.f32 "
        "{%0,%1,%2,%3},{%4,%5,%6,%7},{%8,%9},{%0,%1,%2,%3};"
        : "+f"(c[0]), "+f"(c[1]), "+f"(c[2]), "+f"(c[3])
        : "r"(a[0]), "r"(a[1]), "r"(a[2]), "r"(a[3]), "r"(b0), "r"(b1));
}

// ---------------- compile-time twiddles (units of 2*pi/64) ------------------
__device__ __host__ constexpr float TWQ_(int i) {
    constexpr float q[17] = {
        1.000000000f, 0.995184727f, 0.980785280f, 0.956940336f,
        0.923879533f, 0.881921264f, 0.831469612f, 0.773010453f,
        0.707106781f, 0.634393284f, 0.555570233f, 0.471396737f,
        0.382683432f, 0.290284677f, 0.195090322f, 0.098017140f, 0.f };
    return q[i];
}
__device__ __host__ constexpr float twcos(int j) {
    j &= 63;
    if (j <= 16) return TWQ_(j);
    if (j <= 32) return -TWQ_(32 - j);
    if (j <= 48) return -TWQ_(j - 32);
    return TWQ_(64 - j);
}
__device__ __host__ constexpr float twsin(int j) { return twcos(j + 48); }
__device__ __host__ constexpr int brevN(int n, int bits) {
    int r = 0;
    for (int b = 0; b < bits; b++) r |= ((n >> b) & 1) << (bits - 1 - b);
    return r;
}

template<int SGN, int LOGN>
__device__ __forceinline__ void fftreg(float* xr, float* xi) {
    const int N = 1 << LOGN;
    #pragma unroll
    for (int n = 1; n < N; n++) {
        const int r = brevN(n, LOGN);
        if (r > n) {
            float a = xr[n]; xr[n] = xr[r]; xr[r] = a;
            float b = xi[n]; xi[n] = xi[r]; xi[r] = b;
        }
    }
    #pragma unroll
    for (int s = 0; s < LOGN; s++) {
        const int half = 1 << s;
        #pragma unroll
        for (int j = 0; j < N/2; j++) {
            const int k  = j & (half - 1);
            const int g  = j >> s;
            const int i1 = g * (half << 1) + k;
            const int i2 = i1 + half;
            const float wr = twcos(k << (5 - s));
            const float wi = (float)SGN * twsin(k << (5 - s));
            float vr = xr[i2], vi = xi[i2];
            float tr = vr * wr - vi * wi;
            float ti = vr * wi + vi * wr;
            float ur = xr[i1], ui = xi[i1];
            xr[i1] = ur + tr;  xi[i1] = ui + ti;
            xr[i2] = ur - tr;  xi[i2] = ui - ti;
        }
    }
}

__device__ __forceinline__ float sigm(float v) { return 1.f / (1.f + __expf(-v)); }
__device__ __forceinline__ float ftanh(float v) { return 2.f / (1.f + __expf(-2.f*v)) - 1.f; }
__device__ __forceinline__ float2 h2f(__half2 h) { return __half22float2(h); }

// ================= 2-way split packed real-FFT pipeline ======================
__device__ __forceinline__ void irfft_build2(const __half2* __restrict__ A,
                                             int t, int hseg, float* zr, float* zi) {
    if (!hseg) {
        float2 x0  = h2f(A[t]);
        float2 x32 = h2f(A[32*64 + t]);
        float2 x16 = h2f(A[16*64 + t]);
        zr[0] = 0.5f*(x0.x + x32.x);   zi[0] = 0.5f*(x0.x - x32.x);
        zr[8] = x16.x;                 zi[8] = -x16.y;
        #pragma unroll
        for (int k = 2; k <= 14; k += 2) {
            float2 a = h2f(A[k*64 + t]);
            float2 b = h2f(A[(32-k)*64 + t]);
            float Sr = 0.5f*(a.x + b.x), Si = 0.5f*(a.y - b.y);
            float Dr = 0.5f*(a.x - b.x), Di = 0.5f*(a.y + b.y);
            const float c = twcos(k), s = twsin(k);
            float XoR = c*Dr - s*Di;
            float XoI = c*Di + s*Dr;
            zr[k/2]    = Sr - XoI;  zi[k/2]    = Si + XoR;
            zr[16-k/2] = Sr + XoI;  zi[16-k/2] = XoR - Si;
        }
    } else {
        #pragma unroll
        for (int k = 1; k <= 15; k += 2) {
            float2 a = h2f(A[k*64 + t]);
            float2 b = h2f(A[(32-k)*64 + t]);
            float Sr = 0.5f*(a.x + b.x), Si = 0.5f*(a.y - b.y);
            float Dr = 0.5f*(a.x - b.x), Di = 0.5f*(a.y + b.y);
            const float c = twcos(k), s = twsin(k);
            float XoR = c*Dr - s*Di;
            float XoI = c*Di + s*Dr;
            zr[(k-1)/2]      = Sr - XoI;  zi[(k-1)/2]      = Si + XoR;
            zr[15-(k-1)/2]   = Sr + XoI;  zi[15-(k-1)/2]   = XoR - Si;
        }
    }
    fftreg<1,4>(zr, zi);
    #pragma unroll
    for (int j = 0; j < 16; j++) {
        float br = __shfl_xor_sync(0xffffffffu, zr[j], 16);
        float bi = __shfl_xor_sync(0xffffffffu, zi[j], 16);
        const float c = twcos(2*j), s = twsin(2*j);
        if (!hseg) { zr[j] += br*c - bi*s;  zi[j] += br*s + bi*c; }
        else {
            float tr = zr[j]*c - zi[j]*s, ti = zr[j]*s + zi[j]*c;
            zr[j] = br - tr;  zi[j] = bi - ti;
        }
    }
}

__device__ __forceinline__ void rfft_store2(__half2* __restrict__ out,
                                            int t, int hseg, float* zr, float* zi) {
    #pragma unroll
    for (int j = 0; j < 16; j++) {
        float br = __shfl_xor_sync(0xffffffffu, zr[j], 16);
        float bi = __shfl_xor_sync(0xffffffffu, zi[j], 16);
        if (!hseg) { zr[j] += br;  zi[j] += bi; }
        else {
            float dr = br - zr[j], di = bi - zi[j];
            const float c = twcos(2*j), s = twsin(2*j);
            zr[j] = dr*c + di*s;
            zi[j] = di*c - dr*s;
        }
    }
    fftreg<-1,4>(zr, zi);
    if (!hseg) {
        out[0*64 + t]  = __floats2half2_rn(zr[0] + zi[0], 0.f);
        out[32*64 + t] = __floats2half2_rn(zr[0] - zi[0], 0.f);
        out[16*64 + t] = __floats2half2_rn(zr[8], -zi[8]);
        #pragma unroll
        for (int k = 2; k <= 14; k += 2) {
            const int m = k/2, mq = 16 - k/2;
            float XeR = 0.5f*(zr[m] + zr[mq]), XeI = 0.5f*(zi[m] - zi[mq]);
            float XoR = 0.5f*(zi[m] + zi[mq]), XoI = 0.5f*(zr[mq] - zr[m]);
            const float c = twcos(k), s = twsin(k);
            float wXoR = c*XoR + s*XoI;
            float wXoI = c*XoI - s*XoR;
            out[k*64 + t]      = __floats2half2_rn(XeR + wXoR, XeI + wXoI);
            out[(32-k)*64 + t] = __floats2half2_rn(XeR - wXoR, -(XeI - wXoI));
        }
    } else {
        #pragma unroll
        for (int k = 1; k <= 15; k += 2) {
            const int m = (k-1)/2, mq = 15 - (k-1)/2;
            float XeR = 0.5f*(zr[m] + zr[mq]), XeI = 0.5f*(zi[m] - zi[mq]);
            float XoR = 0.5f*(zi[m] + zi[mq]), XoI = 0.5f*(zr[mq] - zr[m]);
            const float c = twcos(k), s = twsin(k);
            float wXoR = c*XoR + s*XoI;
            float wXoI = c*XoI - s*XoR;
            out[k*64 + t]      = __floats2half2_rn(XeR + wXoR, XeI + wXoI);
            out[(32-k)*64 + t] = __floats2half2_rn(XeR - wXoR, -(XeI - wXoI));
        }
    }
}

// ---- single-thread forward rfft (prologue only) ----------------------------
__device__ __forceinline__ void rfft_store1(__half2* __restrict__ out, int t,
                                            float* zr, float* zi) {
    fftreg<-1,5>(zr, zi);
    out[0*64 + t]  = __floats2half2_rn(zr[0] + zi[0], 0.f);
    out[32*64 + t] = __floats2half2_rn(zr[0] - zi[0], 0.f);
    out[16*64 + t] = __floats2half2_rn(zr[16], -zi[16]);
    #pragma unroll
    for (int k = 1; k < 16; k++) {
        const int q = 32 - k;
        float XeR = 0.5f*(zr[k] + zr[q]), XeI = 0.5f*(zi[k] - zi[q]);
        float XoR = 0.5f*(zi[k] + zi[q]), XoI = 0.5f*(zr[q] - zr[k]);
        const float c = twcos(k), s = twsin(k);
        float wXoR = c*XoR + s*XoI;
        float wXoI = c*XoI - s*XoR;
        out[k*64 + t] = __floats2half2_rn(XeR + wXoR, XeI + wXoI);
        out[q*64 + t] = __floats2half2_rn(XeR - wXoR, -(XeI - wXoI));
    }
}

// ---------------- weight transpose: [i][o][f] -> [f][p][w=i][o] compact fp16 -
__global__ void k_wt_all(const float* __restrict__ p0r, const float* __restrict__ p0i,
                         const float* __restrict__ p1r, const float* __restrict__ p1i,
                         const float* __restrict__ p2r, const float* __restrict__ p2i) {
    __shared__ float s_r[64*65];
    __shared__ float s_i[64*65];
    int gate = blockIdx.z;
    const float* wr = gate == 0 ? p0r : (gate == 1 ? p1r : p2r);
    const float* wi = gate == 0 ? p0i : (gate == 1 ? p1i : p2i);
    int f0  = blockIdx.x * 64;
    int io0 = blockIdx.y * 64;
    int lane = threadIdx.x & 63;
    int row  = threadIdx.x >> 6;
    #pragma unroll
    for (int r = row; r < 64; r += 4) {
        s_r[r*65 + lane] = wr[(size_t)(io0 + r) * NF + f0 + lane];
        s_i[r*65 + lane] = wi[(size_t)(io0 + r) * NF + f0 + lane];
    }
    __syncthreads();
    __half* out = d_Wt[gate];
    #pragma unroll
    for (int fl = row; fl < 64; fl += 4) {
        size_t base = (size_t)(f0 + fl) * WFS + (size_t)blockIdx.y * 64 + lane;
        out[base]        = __float2half_rn(s_r[lane*65 + fl]);
        out[base + 4096] = __float2half_rn(s_i[lane*65 + fl]);
    }
}

// ---------------- h0 = x @ Wi + bi (CIN=1) ----------------------------------
__global__ void k_init_h(const float* __restrict__ x, const float* __restrict__ Wi,
                         const float* __restrict__ bi) {
    int idx = blockIdx.x * 256 + threadIdx.x;
    int bw = idx >> 12;
    int xy = idx & 4095;
    int b = bw >> 6, w = bw & 63;
    d_h[idx] = x[b * TILE + xy] * Wi[w] + bi[w];
}

// ---------------- prologue: y-rfft of h (runs once) --------------------------
__global__ void k_fwd1() {
    int bw = blockIdx.x, t = threadIdx.x;
    const float4* row = reinterpret_cast<const float4*>(d_h + (size_t)bw * TILE + t*64);
    float zr[32], zi[32];
    #pragma unroll
    for (int j = 0; j < 16; j++) {
        float4 v = row[j];
        zr[2*j] = v.x; zi[2*j] = v.y; zr[2*j+1] = v.z; zi[2*j+1] = v.w;
    }
    rfft_store1(d_A1 + (size_t)bw * YHN * 64, t, zr, zi);
}

// ---------------- x-FFT (4-way DIF, ILP2 over bw): d_A1 -> d_Hf --------------
__global__ void k_fwd2() {
    pdl_wait();
    int k = blockIdx.x;
    int lane = threadIdx.x & 31;
    int wid  = threadIdx.x >> 5;
    int q = lane >> 3;
    int r = lane & 7;
    int bw0 = blockIdx.y * 64 + wid * 16 + r;   // second line: bw0 + 8
    bool qlo1 = (q < 2);
    bool qodd = (q & 1);

    float ar[2][16], ai[2][16];
    #pragma unroll
    for (int s = 0; s < 2; s++) {
        const uint4* src = reinterpret_cast<const uint4*>(
            d_A1 + ((size_t)(bw0 + 8*s)*YHN + k)*64 + 16*q);
        #pragma unroll
        for (int j = 0; j < 4; j++) {
            uint4 v = src[j];
            float2 c0 = h2f(*reinterpret_cast<__half2*>(&v.x));
            float2 c1 = h2f(*reinterpret_cast<__half2*>(&v.y));
            float2 c2 = h2f(*reinterpret_cast<__half2*>(&v.z));
            float2 c3 = h2f(*reinterpret_cast<__half2*>(&v.w));
            ar[s][4*j+0] = c0.x; ai[s][4*j+0] = c0.y;
            ar[s][4*j+1] = c1.x; ai[s][4*j+1] = c1.y;
            ar[s][4*j+2] = c2.x; ai[s][4*j+2] = c2.y;
            ar[s][4*j+3] = c3.x; ai[s][4*j+3] = c3.y;
        }
    }
    #pragma unroll
    for (int j = 0; j < 16; j++) {
        const float cj = twcos(j), sj = twsin(j);
        const float c = qodd ? -sj : cj;
        const float s = qodd ?  cj : sj;
        #pragma unroll
        for (int st = 0; st < 2; st++) {
            float br = __shfl_xor_sync(0xffffffffu, ar[st][j], 16);
            float bi = __shfl_xor_sync(0xffffffffu, ai[st][j], 16);
            if (qlo1) { ar[st][j] += br;  ai[st][j] += bi; }
            else {
                float dr = br - ar[st][j], di = bi - ai[st][j];
                ar[st][j] = dr*c + di*s;
                ai[st][j] = di*c - dr*s;
            }
        }
    }
    #pragma unroll
    for (int j = 0; j < 16; j++) {
        const float c = twcos(2*j), s = twsin(2*j);
        #pragma unroll
        for (int st = 0; st < 2; st++) {
            float br = __shfl_xor_sync(0xffffffffu, ar[st][j], 8);
            float bi = __shfl_xor_sync(0xffffffffu, ai[st][j], 8);
            if (!qodd) { ar[st][j] += br;  ai[st][j] += bi; }
            else {
                float dr = br - ar[st][j], di = bi - ai[st][j];
                ar[st][j] = dr*c + di*s;
                ai[st][j] = di*c - dr*s;
            }
        }
    }
    fftreg<-1,4>(ar[0], ai[0]);
    fftreg<-1,4>(ar[1], ai[1]);
    pdl_trigger();
    int cq = ((q & 1) << 1) | (q >> 1);
    #pragma unroll
    for (int m = 0; m < 16; m++) {
        size_t base = ((size_t)(4*m + cq)*YHN + k)*BWN;
        d_Hf[base + bw0]     = __floats2half2_rn(ar[0][m], ai[0][m]);
        d_Hf[base + bw0 + 8] = __floats2half2_rn(ar[1][m], ai[1][m]);
    }
}

// ---------------- per-frequency complex GEMM via tensor cores ----------------
__global__ void k_gemm(int pass) {
    int f = blockIdx.x;
    __shared__ __align__(16) __half sHr[16*LDH];
    __shared__ __align__(16) __half sHi[16*LDH];
    __shared__ __align__(16) __half sW[2*64*LDW];
    int tid = threadIdx.x;             // 128
    int lane = tid & 31, wid = tid >> 5;
    const int ngates = (pass == 0) ? 2 : 1;
    const int gb = (pass == 0) ? 0 : 2;

    // pre-wait prologue: stage gate-0 weights (independent of predecessor)
    {
        const uint4* src = reinterpret_cast<const uint4*>(d_Wt[gb] + (size_t)f * WFS);
        uint4* dst = reinterpret_cast<uint4*>(sW);
        #pragma unroll
        for (int i = tid; i < 1024; i += 128) dst[(i >> 3)*9 + (i & 7)] = src[i];
    }
    pdl_wait();
    {
        const __half2* Hsrc = d_Hf + (size_t)f * BWN;
        #pragma unroll
        for (int i = tid; i < BWN; i += 128) {
            __half2 v = Hsrc[i];
            int b = i >> 6, w = i & 63;
            sHr[b*LDH + w] = __low2half(v);
            sHi[b*LDH + w] = __high2half(v);
        }
    }
    __syncthreads();

    const int obase = wid * 16;
    const u32 baseHr = smem_u32(sHr);
    const u32 baseHi = smem_u32(sHi);
    const u32 baseW  = smem_u32(sW);
    const int arow = lane & 15, acol = (lane >> 4) * 8;

    for (int g = 0; g < ngates; g++) {
        __half2* O = (pass == 0 && g == 1) ? d_F1 : d_F0;

        float cr[2][4] = {{0.f,0.f,0.f,0.f},{0.f,0.f,0.f,0.f}};
        float ci[2][4] = {{0.f,0.f,0.f,0.f},{0.f,0.f,0.f,0.f}};

        #pragma unroll
        for (int kk = 0; kk < 4; kk++) {
            u32 Ar[4], Ai[4], An[4];
            u32 aoff = (u32)((arow*LDH + kk*16 + acol) * 2);
            ldsm_x4(Ar[0], Ar[1], Ar[2], Ar[3], baseHr + aoff);
            ldsm_x4(Ai[0], Ai[1], Ai[2], Ai[3], baseHi + aoff);
            #pragma unroll
            for (int j = 0; j < 4; j++) An[j] = Ai[j] ^ 0x80008000u;

            u32 Br[4], Bi[4];
            u32 boff = (u32)(((kk*16 + (lane & 15))*LDW
                              + obase + (lane >> 4)*8) * 2);
            ldsm_x4t(Br[0], Br[1], Br[2], Br[3], baseW + boff);
            ldsm_x4t(Bi[0], Bi[1], Bi[2], Bi[3], baseW + (u32)(64*LDW*2) + boff);

            #pragma unroll
            for (int nt = 0; nt < 2; nt++) {
                mma16816(cr[nt], Ar, Br[2*nt], Br[2*nt+1]);
                mma16816(cr[nt], An, Bi[2*nt], Bi[2*nt+1]);
                mma16816(ci[nt], Ar, Bi[2*nt], Bi[2*nt+1]);
                mma16816(ci[nt], Ai, Br[2*nt], Br[2*nt+1]);
            }
        }

        if (g == ngates - 1) pdl_trigger();
        __half2* Of = O + (size_t)f * BWN;
        int b0 = lane >> 2, oc = (lane & 3) * 2;
        #pragma unroll
        for (int nt = 0; nt < 2; nt++) {
            int o = obase + nt*8 + oc;
            __half2 p00 = __floats2half2_rn(cr[nt][0], ci[nt][0]);
            __half2 p01 = __floats2half2_rn(cr[nt][1], ci[nt][1]);
            uint2 u0;
            u0.x = *reinterpret_cast<u32*>(&p00);
            u0.y = *reinterpret_cast<u32*>(&p01);
            *reinterpret_cast<uint2*>(Of + b0*64 + o) = u0;
            __half2 p10 = __floats2half2_rn(cr[nt][2], ci[nt][2]);
            __half2 p11 = __floats2half2_rn(cr[nt][3], ci[nt][3]);
            uint2 u1;
            u1.x = *reinterpret_cast<u32*>(&p10);
            u1.y = *reinterpret_cast<u32*>(&p11);
            *reinterpret_cast<uint2*>(Of + (b0+8)*64 + o) = u1;
        }
        if (g + 1 < ngates) {
            __syncthreads();
            const uint4* src = reinterpret_cast<const uint4*>(
                d_Wt[gb + g + 1] + (size_t)f * WFS);
            uint4* dst = reinterpret_cast<uint4*>(sW);
            #pragma unroll
            for (int i = tid; i < 1024; i += 128) dst[(i >> 3)*9 + (i & 7)] = src[i];
            __syncthreads();
        }
    }
}

// ---------------- inverse x-FFT (4-way DIT, ILP2 over bw): d_F -> d_Ax -------
__global__ void k_inv1(int pass) {
    pdl_wait();
    int k = blockIdx.x;
    int lane = threadIdx.x & 31;
    int wid  = threadIdx.x >> 5;
    int q = lane >> 3;
    int r = lane & 7;
    int bw0 = blockIdx.y * 64 + wid * 16 + r;
    bool qlo1 = (q < 2);
    bool qodd = (q & 1);
    const __half2* F = (pass == 0 && blockIdx.z == 1) ? d_F1 : d_F0;
    __half2* A = (pass == 1 || blockIdx.z == 1) ? d_Ax1 : d_Ax0;

    int cq = ((q & 1) << 1) | (q >> 1);
    float ar[2][16], ai[2][16];
    #pragma unroll
    for (int m = 0; m < 16; m++) {
        size_t base = ((size_t)(4*m + cq)*YHN + k)*BWN;
        float2 v0 = h2f(F[base + bw0]);
        float2 v1 = h2f(F[base + bw0 + 8]);
        ar[0][m] = v0.x; ai[0][m] = v0.y;
        ar[1][m] = v1.x; ai[1][m] = v1.y;
    }
    fftreg<1,4>(ar[0], ai[0]);
    fftreg<1,4>(ar[1], ai[1]);
    #pragma unroll
    for (int j = 0; j < 16; j++) {
        const float c = twcos(2*j), s = twsin(2*j);
        #pragma unroll
        for (int st = 0; st < 2; st++) {
            float br = __shfl_xor_sync(0xffffffffu, ar[st][j], 8);
            float bi = __shfl_xor_sync(0xffffffffu, ai[st][j], 8);
            if (!qodd) { ar[st][j] += br*c - bi*s;  ai[st][j] += br*s + bi*c; }
            else {
                float tr = ar[st][j]*c - ai[st][j]*s, ti = ar[st][j]*s + ai[st][j]*c;
                ar[st][j] = br - tr;  ai[st][j] = bi - ti;
            }
        }
    }
    #pragma unroll
    for (int j = 0; j < 16; j++) {
        const float cj = twcos(j), sj = twsin(j);
        const float c = qodd ? -sj : cj;
        const float s = qodd ?  cj : sj;
        #pragma unroll
        for (int st = 0; st < 2; st++) {
            float br = __shfl_xor_sync(0xffffffffu, ar[st][j], 16);
            float bi = __shfl_xor_sync(0xffffffffu, ai[st][j], 16);
            if (qlo1) { ar[st][j] += br*c - bi*s;  ai[st][j] += br*s + bi*c; }
            else {
                float tr = ar[st][j]*c - ai[st][j]*s, ti = ar[st][j]*s + ai[st][j]*c;
                ar[st][j] = br - tr;  ai[st][j] = bi - ti;
            }
        }
    }
    pdl_trigger();
    #pragma unroll
    for (int st = 0; st < 2; st++) {
        uint2* dst = reinterpret_cast<uint2*>(
            A + ((size_t)(bw0 + 8*st)*YHN + k)*64 + 16*q);
        #pragma unroll
        for (int j = 0; j < 8; j++) {
            __half2 h0 = __floats2half2_rn(ar[st][2*j],   ai[st][2*j]);
            __half2 h1 = __floats2half2_rn(ar[st][2*j+1], ai[st][2*j+1]);
            uint2 u;
            u.x = *reinterpret_cast<u32*>(&h0);
            u.y = *reinterpret_cast<u32*>(&h1);
            dst[j] = u;
        }
    }
}

// ---------------- fused: g = sigm(irfft(Ax1))*h, y-rfft(g) -------------------
__global__ void k_fused_zr() {
    pdl_wait();
    int bw = blockIdx.x;
    int lane = threadIdx.x & 31, wid = threadIdx.x >> 5;
    int t = wid*16 + (lane & 15);
    int hseg = lane >> 4;
    const float sc = 1.f / 2048.f;
    float zr[16], zi[16];
    irfft_build2(d_Ax1 + (size_t)bw * YHN * 64, t, hseg, zr, zi);
    const float4* hrow = reinterpret_cast<const float4*>(
        d_h + (size_t)bw * TILE + t*64 + 32*hseg);
    #pragma unroll
    for (int j = 0; j < 8; j++) {
        float4 h4 = hrow[j];
        zr[2*j]   = h4.x * sigm(zr[2*j]*sc);
        zi[2*j]   = h4.y * sigm(zi[2*j]*sc);
        zr[2*j+1] = h4.z * sigm(zr[2*j+1]*sc);
        zi[2*j+1] = h4.w * sigm(zi[2*j+1]*sc);
    }
    pdl_trigger();
    rfft_store2(d_A1 + (size_t)bw * YHN * 64, t, hseg, zr, zi);
}

// ---------------- fused: z = sigm(irfft(Ax0)), h += z(tanh(irfft(Ax1)) - h) --
__global__ void k_fused_h(int last) {
    pdl_wait();
    int bw = blockIdx.x;
    int lane = threadIdx.x & 31, wid = threadIdx.x >> 5;
    int t = wid*16 + (lane & 15);
    int hseg = lane >> 4;
    const float sc = 1.f / 2048.f;
    float zvr[16], zvi[16];
    irfft_build2(d_Ax0 + (size_t)bw * YHN * 64, t, hseg, zvr, zvi);
    #pragma unroll
    for (int j = 0; j < 16; j++) { zvr[j] = sigm(zvr[j]*sc); zvi[j] = sigm(zvi[j]*sc); }
    float nr[16], ni[16];
    irfft_build2(d_Ax1 + (size_t)bw * YHN * 64, t, hseg, nr, ni);
    pdl_trigger();
    float4* hrow = reinterpret_cast<float4*>(
        d_h + (size_t)bw * TILE + t*64 + 32*hseg);
    #pragma unroll
    for (int j = 0; j < 8; j++) {
        float4 h4 = hrow[j];
        float n0 = ftanh(nr[2*j]*sc),   n1 = ftanh(ni[2*j]*sc);
        float n2 = ftanh(nr[2*j+1]*sc), n3 = ftanh(ni[2*j+1]*sc);
        h4.x += zvr[2*j]   * (n0 - h4.x);
        h4.y += zvi[2*j]   * (n1 - h4.y);
        h4.z += zvr[2*j+1] * (n2 - h4.z);
        h4.w += zvi[2*j+1] * (n3 - h4.w);
        hrow[j] = h4;
        nr[2*j] = h4.x; ni[2*j] = h4.y; nr[2*j+1] = h4.z; ni[2*j+1] = h4.w;
    }
    if (!last)
        rfft_store2(d_A1 + (size_t)bw * YHN * 64, t, hseg, nr, ni);
}

// ---------------- out mapping: y = h @ Wo + bo (4-way w-split) ---------------
__global__ void k_out(const float* __restrict__ Wo, const float* __restrict__ bo,
                      float* __restrict__ out, int t) {
    __shared__ float sp[3*256];
    pdl_wait();
    int b = blockIdx.x;
    int xyl = threadIdx.x & 255;
    int xy = blockIdx.y * 256 + xyl;
    int wq = threadIdx.x >> 8;       // 0..3
    float acc = 0.f;
    const float* hb = d_h + (size_t)(b*64 + wq*16) * TILE + xy;
    #pragma unroll
    for (int w = 0; w < 16; w++)
        acc += hb[(size_t)w * TILE] * __ldg(&Wo[wq*16 + w]);
    if (wq > 0) sp[(wq-1)*256 + xyl] = acc;
    __syncthreads();
    pdl_trigger();   // `out` is not read by any dependent kernel
    if (wq == 0) {
        acc += sp[xyl] + sp[256 + xyl] + sp[512 + xyl] + bo[0];
        out[(size_t)(b*TT + t) * TILE + xy] = acc;
    }
}

// ---------------- PDL launch helper ------------------------------------------
template<typename... A, typename... B>
static inline void pdl_launch(void(*kern)(A...), dim3 grid, dim3 block, B... args) {
    cudaLaunchConfig_t cfg = {};
    cfg.gridDim = grid;
    cfg.blockDim = block;
    cfg.stream = 0;
    cudaLaunchAttribute at[1];
    at[0].id = cudaLaunchAttributeProgrammaticStreamSerialization;
    at[0].val.programmaticStreamSerializationAllowed = 1;
    cfg.attrs = at;
    cfg.numAttrs = 1;
    cudaLaunchKernelEx(&cfg, kern, (A)args...);
}

// ---------------- launch -----------------------------------------------------
extern "C" void kernel_launch(void* const* d_in, const int* in_sizes, int n_in,
                              void* d_out, int out_size) {
    int iX = 0, iWi = 2, iBi = 3, iWo = 4, iBo = 5, iWz = 6;
    if (n_in == 11) { iWi = 1; iBi = 2; iWo = 3; iBo = 4; iWz = 5; }

    const float* x    = (const float*)d_in[iX];
    const float* Wi   = (const float*)d_in[iWi];
    const float* bi   = (const float*)d_in[iBi];
    const float* Wo   = (const float*)d_in[iWo];
    const float* bo   = (const float*)d_in[iBo];
    float* out = (float*)d_out;

    k_wt_all<<<dim3(33, 64, 3), 256>>>((const float*)d_in[iWz+0], (const float*)d_in[iWz+1],
                                       (const float*)d_in[iWz+2], (const float*)d_in[iWz+3],
                                       (const float*)d_in[iWz+4], (const float*)d_in[iWz+5]);
    k_init_h<<<(BWN*TILE)/256, 256>>>(x, Wi, bi);
    k_fwd1<<<BWN, 64>>>();
    k_fwd2<<<dim3(YHN, 16), 128>>>();

    for (int t = 0; t < TT; t++) {
        pdl_launch(k_gemm, dim3(NF), dim3(128), 0);              // z->F0, r->F1
        pdl_launch(k_inv1, dim3(YHN, 16, 2), dim3(128), 0);      // F0->Ax0, F1->Ax1
        pdl_launch(k_fused_zr, dim3(BWN), dim3(128));            // g = r*h, y-rfft
        pdl_launch(k_fwd2, dim3(YHN, 16), dim3(128));            // x-FFT(g) -> Hf
        pdl_launch(k_gemm, dim3(NF), dim3(128), 1);              // nh -> F0
        pdl_launch(k_inv1, dim3(YHN, 16, 1), dim3(128), 1);      // F0 -> Ax1
        pdl_launch(k_fused_h, dim3(BWN), dim3(128), (int)(t == TT-1));
        if (t < TT-1) pdl_launch(k_fwd2, dim3(YHN, 16), dim3(128));
        pdl_launch(k_out, dim3(BB, TILE/256), dim3(1024), Wo, bo, out, t);
    }
}

// round 14
// speedup vs baseline: 1.0231x; 1.0231x over previous
#include <cuda_runtime.h>
#include <cuda_fp16.h>
#include <math.h>

#define BB   16
#define WWC  64
#define TT   20
#define YHN  33
#define NF   2112          // 64 * 33
#define BWN  1024          // BB * WWC
#define TILE 4096
#define LDH  72            // H smem row stride in halfs (144B, bank-rotating)
#define LDW  72            // W smem row stride in halfs
#define WFS  8192          // halfs per f per gate in GLOBAL (compact): 2*64*64

typedef unsigned int u32;

// ---------------- device scratch ------------------------------------------
static __device__ float  d_h [BWN*TILE];
static __device__ __align__(16) __half2 d_A1 [(size_t)BWN*YHN*64];   // [bw][k][x]
static __device__ __align__(16) __half2 d_Hf [(size_t)NF*BWN];       // [f][bw]
static __device__ __align__(16) __half2 d_F0 [(size_t)NF*BWN];
static __device__ __align__(16) __half2 d_F1 [(size_t)NF*BWN];
static __device__ __align__(16) __half2 d_Ax0[(size_t)BWN*YHN*64];   // [bw][k][x]
static __device__ __align__(16) __half2 d_Ax1[(size_t)BWN*YHN*64];
static __device__ __align__(16) __half  d_Wt [3][(size_t)NF*WFS];    // [f][p][w][o] compact

// ---------------- PDL helpers -------------------------------------------------
__device__ __forceinline__ void pdl_wait()    { asm volatile("griddepcontrol.wait;" ::: "memory"); }
__device__ __forceinline__ void pdl_trigger() { asm volatile("griddepcontrol.launch_dependents;" ::: "memory"); }

// ---------------- mma / ldmatrix helpers -------------------------------------
__device__ __forceinline__ u32 smem_u32(const void* p) {
    return (u32)__cvta_generic_to_shared(p);
}
__device__ __forceinline__ void ldsm_x4(u32& r0, u32& r1, u32& r2,
                                        u32& r3, u32 addr) {
    asm volatile("ldmatrix.sync.aligned.m8n8.x4.shared.b16 {%0,%1,%2,%3},[%4];"
                 : "=r"(r0), "=r"(r1), "=r"(r2), "=r"(r3) : "r"(addr));
}
__device__ __forceinline__ void ldsm_x4t(u32& r0, u32& r1, u32& r2,
                                         u32& r3, u32 addr) {
    asm volatile("ldmatrix.sync.aligned.m8n8.x4.trans.shared.b16 {%0,%1,%2,%3},[%4];"
                 : "=r"(r0), "=r"(r1), "=r"(r2), "=r"(r3) : "r"(addr));
}
__device__ __forceinline__ void mma16816(float* c, const u32* a,
                                         u32 b0, u32 b1) {
    asm volatile(
        "mma.sync.aligned.m16n8k16.row.col.f32.f16.f16.f32 "
        "{%0,%1,%2,%3},{%4,%5,%6,%7},{%8,%9},{%0,%1,%2,%3};"
        : "+f"(c[0]), "+f"(c[1]), "+f"(c[2]), "+f"(c[3])
        : "r"(a[0]), "r"(a[1]), "r"(a[2]), "r"(a[3]), "r"(b0), "r"(b1));
}

// ---------------- compile-time twiddles (units of 2*pi/64) ------------------
__device__ __host__ constexpr float TWQ_(int i) {
    constexpr float q[17] = {
        1.000000000f, 0.995184727f, 0.980785280f, 0.956940336f,
        0.923879533f, 0.881921264f, 0.831469612f, 0.773010453f,
        0.707106781f, 0.634393284f, 0.555570233f, 0.471396737f,
        0.382683432f, 0.290284677f, 0.195090322f, 0.098017140f, 0.f };
    return q[i];
}
__device__ __host__ constexpr float twcos(int j) {
    j &= 63;
    if (j <= 16) return TWQ_(j);
    if (j <= 32) return -TWQ_(32 - j);
    if (j <= 48) return -TWQ_(j - 32);
    return TWQ_(64 - j);
}
__device__ __host__ constexpr float twsin(int j) { return twcos(j + 48); }
__device__ __host__ constexpr int brevN(int n, int bits) {
    int r = 0;
    for (int b = 0; b < bits; b++) r |= ((n >> b) & 1) << (bits - 1 - b);
    return r;
}

template<int SGN, int LOGN>
__device__ __forceinline__ void fftreg(float* xr, float* xi) {
    const int N = 1 << LOGN;
    #pragma unroll
    for (int n = 1; n < N; n++) {
        const int r = brevN(n, LOGN);
        if (r > n) {
            float a = xr[n]; xr[n] = xr[r]; xr[r] = a;
            float b = xi[n]; xi[n] = xi[r]; xi[r] = b;
        }
    }
    #pragma unroll
    for (int s = 0; s < LOGN; s++) {
        const int half = 1 << s;
        #pragma unroll
        for (int j = 0; j < N/2; j++) {
            const int k  = j & (half - 1);
            const int g  = j >> s;
            const int i1 = g * (half << 1) + k;
            const int i2 = i1 + half;
            const float wr = twcos(k << (5 - s));
            const float wi = (float)SGN * twsin(k << (5 - s));
            float vr = xr[i2], vi = xi[i2];
            float tr = vr * wr - vi * wi;
            float ti = vr * wi + vi * wr;
            float ur = xr[i1], ui = xi[i1];
            xr[i1] = ur + tr;  xi[i1] = ui + ti;
            xr[i2] = ur - tr;  xi[i2] = ui - ti;
        }
    }
}

__device__ __forceinline__ float sigm(float v) { return 1.f / (1.f + __expf(-v)); }
__device__ __forceinline__ float ftanh(float v) { return 2.f / (1.f + __expf(-2.f*v)) - 1.f; }
__device__ __forceinline__ float2 h2f(__half2 h) { return __half22float2(h); }

// ================= 2-way split packed real-FFT pipeline ======================
__device__ __forceinline__ void irfft_build2(const __half2* __restrict__ A,
                                             int t, int hseg, float* zr, float* zi) {
    if (!hseg) {
        float2 x0  = h2f(A[t]);
        float2 x32 = h2f(A[32*64 + t]);
        float2 x16 = h2f(A[16*64 + t]);
        zr[0] = 0.5f*(x0.x + x32.x);   zi[0] = 0.5f*(x0.x - x32.x);
        zr[8] = x16.x;                 zi[8] = -x16.y;
        #pragma unroll
        for (int k = 2; k <= 14; k += 2) {
            float2 a = h2f(A[k*64 + t]);
            float2 b = h2f(A[(32-k)*64 + t]);
            float Sr = 0.5f*(a.x + b.x), Si = 0.5f*(a.y - b.y);
            float Dr = 0.5f*(a.x - b.x), Di = 0.5f*(a.y + b.y);
            const float c = twcos(k), s = twsin(k);
            float XoR = c*Dr - s*Di;
            float XoI = c*Di + s*Dr;
            zr[k/2]    = Sr - XoI;  zi[k/2]    = Si + XoR;
            zr[16-k/2] = Sr + XoI;  zi[16-k/2] = XoR - Si;
        }
    } else {
        #pragma unroll
        for (int k = 1; k <= 15; k += 2) {
            float2 a = h2f(A[k*64 + t]);
            float2 b = h2f(A[(32-k)*64 + t]);
            float Sr = 0.5f*(a.x + b.x), Si = 0.5f*(a.y - b.y);
            float Dr = 0.5f*(a.x - b.x), Di = 0.5f*(a.y + b.y);
            const float c = twcos(k), s = twsin(k);
            float XoR = c*Dr - s*Di;
            float XoI = c*Di + s*Dr;
            zr[(k-1)/2]      = Sr - XoI;  zi[(k-1)/2]      = Si + XoR;
            zr[15-(k-1)/2]   = Sr + XoI;  zi[15-(k-1)/2]   = XoR - Si;
        }
    }
    fftreg<1,4>(zr, zi);
    #pragma unroll
    for (int j = 0; j < 16; j++) {
        float br = __shfl_xor_sync(0xffffffffu, zr[j], 16);
        float bi = __shfl_xor_sync(0xffffffffu, zi[j], 16);
        const float c = twcos(2*j), s = twsin(2*j);
        if (!hseg) { zr[j] += br*c - bi*s;  zi[j] += br*s + bi*c; }
        else {
            float tr = zr[j]*c - zi[j]*s, ti = zr[j]*s + zi[j]*c;
            zr[j] = br - tr;  zi[j] = bi - ti;
        }
    }
}

__device__ __forceinline__ void rfft_store2(__half2* __restrict__ out,
                                            int t, int hseg, float* zr, float* zi) {
    #pragma unroll
    for (int j = 0; j < 16; j++) {
        float br = __shfl_xor_sync(0xffffffffu, zr[j], 16);
        float bi = __shfl_xor_sync(0xffffffffu, zi[j], 16);
        if (!hseg) { zr[j] += br;  zi[j] += bi; }
        else {
            float dr = br - zr[j], di = bi - zi[j];
            const float c = twcos(2*j), s = twsin(2*j);
            zr[j] = dr*c + di*s;
            zi[j] = di*c - dr*s;
        }
    }
    fftreg<-1,4>(zr, zi);
    if (!hseg) {
        out[0*64 + t]  = __floats2half2_rn(zr[0] + zi[0], 0.f);
        out[32*64 + t] = __floats2half2_rn(zr[0] - zi[0], 0.f);
        out[16*64 + t] = __floats2half2_rn(zr[8], -zi[8]);
        #pragma unroll
        for (int k = 2; k <= 14; k += 2) {
            const int m = k/2, mq = 16 - k/2;
            float XeR = 0.5f*(zr[m] + zr[mq]), XeI = 0.5f*(zi[m] - zi[mq]);
            float XoR = 0.5f*(zi[m] + zi[mq]), XoI = 0.5f*(zr[mq] - zr[m]);
            const float c = twcos(k), s = twsin(k);
            float wXoR = c*XoR + s*XoI;
            float wXoI = c*XoI - s*XoR;
            out[k*64 + t]      = __floats2half2_rn(XeR + wXoR, XeI + wXoI);
            out[(32-k)*64 + t] = __floats2half2_rn(XeR - wXoR, -(XeI - wXoI));
        }
    } else {
        #pragma unroll
        for (int k = 1; k <= 15; k += 2) {
            const int m = (k-1)/2, mq = 15 - (k-1)/2;
            float XeR = 0.5f*(zr[m] + zr[mq]), XeI = 0.5f*(zi[m] - zi[mq]);
            float XoR = 0.5f*(zi[m] + zi[mq]), XoI = 0.5f*(zr[mq] - zr[m]);
            const float c = twcos(k), s = twsin(k);
            float wXoR = c*XoR + s*XoI;
            float wXoI = c*XoI - s*XoR;
            out[k*64 + t]      = __floats2half2_rn(XeR + wXoR, XeI + wXoI);
            out[(32-k)*64 + t] = __floats2half2_rn(XeR - wXoR, -(XeI - wXoI));
        }
    }
}

// ---- single-thread forward rfft (prologue only) ----------------------------
__device__ __forceinline__ void rfft_store1(__half2* __restrict__ out, int t,
                                            float* zr, float* zi) {
    fftreg<-1,5>(zr, zi);
    out[0*64 + t]  = __floats2half2_rn(zr[0] + zi[0], 0.f);
    out[32*64 + t] = __floats2half2_rn(zr[0] - zi[0], 0.f);
    out[16*64 + t] = __floats2half2_rn(zr[16], -zi[16]);
    #pragma unroll
    for (int k = 1; k < 16; k++) {
        const int q = 32 - k;
        float XeR = 0.5f*(zr[k] + zr[q]), XeI = 0.5f*(zi[k] - zi[q]);
        float XoR = 0.5f*(zi[k] + zi[q]), XoI = 0.5f*(zr[q] - zr[k]);
        const float c = twcos(k), s = twsin(k);
        float wXoR = c*XoR + s*XoI;
        float wXoI = c*XoI - s*XoR;
        out[k*64 + t] = __floats2half2_rn(XeR + wXoR, XeI + wXoI);
        out[q*64 + t] = __floats2half2_rn(XeR - wXoR, -(XeI - wXoI));
    }
}

// ---------------- weight transpose: [i][o][f] -> [f][p][w=i][o] compact fp16 -
__global__ void k_wt_all(const float* __restrict__ p0r, const float* __restrict__ p0i,
                         const float* __restrict__ p1r, const float* __restrict__ p1i,
                         const float* __restrict__ p2r, const float* __restrict__ p2i) {
    __shared__ float s_r[64*65];
    __shared__ float s_i[64*65];
    int gate = blockIdx.z;
    const float* wr = gate == 0 ? p0r : (gate == 1 ? p1r : p2r);
    const float* wi = gate == 0 ? p0i : (gate == 1 ? p1i : p2i);
    int f0  = blockIdx.x * 64;
    int io0 = blockIdx.y * 64;
    int lane = threadIdx.x & 63;
    int row  = threadIdx.x >> 6;
    #pragma unroll
    for (int r = row; r < 64; r += 4) {
        s_r[r*65 + lane] = wr[(size_t)(io0 + r) * NF + f0 + lane];
        s_i[r*65 + lane] = wi[(size_t)(io0 + r) * NF + f0 + lane];
    }
    __syncthreads();
    __half* out = d_Wt[gate];
    #pragma unroll
    for (int fl = row; fl < 64; fl += 4) {
        size_t base = (size_t)(f0 + fl) * WFS + (size_t)blockIdx.y * 64 + lane;
        out[base]        = __float2half_rn(s_r[lane*65 + fl]);
        out[base + 4096] = __float2half_rn(s_i[lane*65 + fl]);
    }
}

// ---------------- h0 = x @ Wi + bi (CIN=1) ----------------------------------
__global__ void k_init_h(const float* __restrict__ x, const float* __restrict__ Wi,
                         const float* __restrict__ bi) {
    int idx = blockIdx.x * 256 + threadIdx.x;
    int bw = idx >> 12;
    int xy = idx & 4095;
    int b = bw >> 6, w = bw & 63;
    d_h[idx] = x[b * TILE + xy] * Wi[w] + bi[w];
}

// ---------------- prologue: y-rfft of h (runs once) --------------------------
__global__ void k_fwd1() {
    int bw = blockIdx.x, t = threadIdx.x;
    const float4* row = reinterpret_cast<const float4*>(d_h + (size_t)bw * TILE + t*64);
    float zr[32], zi[32];
    #pragma unroll
    for (int j = 0; j < 16; j++) {
        float4 v = row[j];
        zr[2*j] = v.x; zi[2*j] = v.y; zr[2*j+1] = v.z; zi[2*j+1] = v.w;
    }
    rfft_store1(d_A1 + (size_t)bw * YHN * 64, t, zr, zi);
}

// ---------------- x-FFT (8-way DIF): d_A1[bw][k][x] -> d_Hf[f][bw] -----------
// 8 threads per 64-pt line: lane = e*4 + r (e = thread-in-line, r = bw sublane)
__global__ void k_fwd2() {
    pdl_wait();
    int k = blockIdx.x;
    int lane = threadIdx.x & 31;
    int wid  = threadIdx.x >> 5;                // 8 warps
    int e = lane >> 2;                          // 0..7
    int r = lane & 3;
    int bw = blockIdx.y * 32 + wid * 4 + r;

    float ar[8], ai[8];
    const uint4* src = reinterpret_cast<const uint4*>(
        d_A1 + ((size_t)bw*YHN + k)*64 + 8*e);
    #pragma unroll
    for (int j = 0; j < 2; j++) {
        uint4 v = src[j];
        float2 c0 = h2f(*reinterpret_cast<__half2*>(&v.x));
        float2 c1 = h2f(*reinterpret_cast<__half2*>(&v.y));
        float2 c2 = h2f(*reinterpret_cast<__half2*>(&v.z));
        float2 c3 = h2f(*reinterpret_cast<__half2*>(&v.w));
        ar[4*j+0] = c0.x; ai[4*j+0] = c0.y;
        ar[4*j+1] = c1.x; ai[4*j+1] = c1.y;
        ar[4*j+2] = c2.x; ai[4*j+2] = c2.y;
        ar[4*j+3] = c3.x; ai[4*j+3] = c3.y;
    }
    const bool hi1 = (e >= 4);
    const bool hi2 = (e & 2) != 0;
    const bool hi3 = (e & 1) != 0;
    // base rotation for stage 1 twiddle W64^{8(e&3)+j}
    const int b3 = e & 3;
    const float cb = (b3 == 0) ? 1.f : ((b3 == 1) ? 0.70710678f : ((b3 == 2) ? 0.f : -0.70710678f));
    const float sb = (b3 == 0) ? 0.f : ((b3 == 1) ? 0.70710678f : ((b3 == 2) ? 1.f :  0.70710678f));
    // stage 1 (dist 32, xor16)
    #pragma unroll
    for (int j = 0; j < 8; j++) {
        float br = __shfl_xor_sync(0xffffffffu, ar[j], 16);
        float bi = __shfl_xor_sync(0xffffffffu, ai[j], 16);
        if (!hi1) { ar[j] += br;  ai[j] += bi; }
        else {
            float dr = br - ar[j], di = bi - ai[j];
            const float cj = twcos(j), sj = twsin(j);
            float c = cb*cj - sb*sj;
            float s = sb*cj + cb*sj;
            ar[j] = dr*c + di*s;
            ai[j] = di*c - dr*s;
        }
    }
    // stage 2 (dist 16, xor8): twiddle W64^{16(e&1)+2j}
    #pragma unroll
    for (int j = 0; j < 8; j++) {
        float br = __shfl_xor_sync(0xffffffffu, ar[j], 8);
        float bi = __shfl_xor_sync(0xffffffffu, ai[j], 8);
        if (!hi2) { ar[j] += br;  ai[j] += bi; }
        else {
            float dr = br - ar[j], di = bi - ai[j];
            const float c2 = twcos(2*j), s2 = twsin(2*j);
            float c = hi3 ? -s2 : c2;
            float s = hi3 ?  c2 : s2;
            ar[j] = dr*c + di*s;
            ai[j] = di*c - dr*s;
        }
    }
    // stage 3 (dist 8, xor4): twiddle W64^{4j}
    #pragma unroll
    for (int j = 0; j < 8; j++) {
        float br = __shfl_xor_sync(0xffffffffu, ar[j], 4);
        float bi = __shfl_xor_sync(0xffffffffu, ai[j], 4);
        if (!hi3) { ar[j] += br;  ai[j] += bi; }
        else {
            float dr = br - ar[j], di = bi - ai[j];
            const float c = twcos(4*j), s = twsin(4*j);
            ar[j] = dr*c + di*s;
            ai[j] = di*c - dr*s;
        }
    }
    fftreg<-1,3>(ar, ai);
    pdl_trigger();
    const int ce = brevN(e, 3);
    #pragma unroll
    for (int m = 0; m < 8; m++)
        d_Hf[((size_t)(8*m + ce)*YHN + k)*BWN + bw] = __floats2half2_rn(ar[m], ai[m]);
}

// ---------------- per-frequency complex GEMM via tensor cores ----------------
__global__ void k_gemm(int pass) {
    int f = blockIdx.x;
    __shared__ __align__(16) __half sHr[16*LDH];
    __shared__ __align__(16) __half sHi[16*LDH];
    __shared__ __align__(16) __half sW[2*64*LDW];
    int tid = threadIdx.x;             // 128
    int lane = tid & 31, wid = tid >> 5;
    const int ngates = (pass == 0) ? 2 : 1;
    const int gb = (pass == 0) ? 0 : 2;

    // pre-wait prologue: stage gate-0 weights (independent of predecessor)
    {
        const uint4* src = reinterpret_cast<const uint4*>(d_Wt[gb] + (size_t)f * WFS);
        uint4* dst = reinterpret_cast<uint4*>(sW);
        #pragma unroll
        for (int i = tid; i < 1024; i += 128) dst[(i >> 3)*9 + (i & 7)] = src[i];
    }
    pdl_wait();
    {
        const __half2* Hsrc = d_Hf + (size_t)f * BWN;
        #pragma unroll
        for (int i = tid; i < BWN; i += 128) {
            __half2 v = Hsrc[i];
            int b = i >> 6, w = i & 63;
            sHr[b*LDH + w] = __low2half(v);
            sHi[b*LDH + w] = __high2half(v);
        }
    }
    __syncthreads();

    const int obase = wid * 16;
    const u32 baseHr = smem_u32(sHr);
    const u32 baseHi = smem_u32(sHi);
    const u32 baseW  = smem_u32(sW);
    const int arow = lane & 15, acol = (lane >> 4) * 8;

    for (int g = 0; g < ngates; g++) {
        __half2* O = (pass == 0 && g == 1) ? d_F1 : d_F0;

        float cr[2][4] = {{0.f,0.f,0.f,0.f},{0.f,0.f,0.f,0.f}};
        float ci[2][4] = {{0.f,0.f,0.f,0.f},{0.f,0.f,0.f,0.f}};

        #pragma unroll
        for (int kk = 0; kk < 4; kk++) {
            u32 Ar[4], Ai[4], An[4];
            u32 aoff = (u32)((arow*LDH + kk*16 + acol) * 2);
            ldsm_x4(Ar[0], Ar[1], Ar[2], Ar[3], baseHr + aoff);
            ldsm_x4(Ai[0], Ai[1], Ai[2], Ai[3], baseHi + aoff);
            #pragma unroll
            for (int j = 0; j < 4; j++) An[j] = Ai[j] ^ 0x80008000u;

            u32 Br[4], Bi[4];
            u32 boff = (u32)(((kk*16 + (lane & 15))*LDW
                              + obase + (lane >> 4)*8) * 2);
            ldsm_x4t(Br[0], Br[1], Br[2], Br[3], baseW + boff);
            ldsm_x4t(Bi[0], Bi[1], Bi[2], Bi[3], baseW + (u32)(64*LDW*2) + boff);

            #pragma unroll
            for (int nt = 0; nt < 2; nt++) {
                mma16816(cr[nt], Ar, Br[2*nt], Br[2*nt+1]);
                mma16816(cr[nt], An, Bi[2*nt], Bi[2*nt+1]);
                mma16816(ci[nt], Ar, Bi[2*nt], Bi[2*nt+1]);
                mma16816(ci[nt], Ai, Br[2*nt], Br[2*nt+1]);
            }
        }

        if (g == ngates - 1) pdl_trigger();
        __half2* Of = O + (size_t)f * BWN;
        int b0 = lane >> 2, oc = (lane & 3) * 2;
        #pragma unroll
        for (int nt = 0; nt < 2; nt++) {
            int o = obase + nt*8 + oc;
            __half2 p00 = __floats2half2_rn(cr[nt][0], ci[nt][0]);
            __half2 p01 = __floats2half2_rn(cr[nt][1], ci[nt][1]);
            uint2 u0;
            u0.x = *reinterpret_cast<u32*>(&p00);
            u0.y = *reinterpret_cast<u32*>(&p01);
            *reinterpret_cast<uint2*>(Of + b0*64 + o) = u0;
            __half2 p10 = __floats2half2_rn(cr[nt][2], ci[nt][2]);
            __half2 p11 = __floats2half2_rn(cr[nt][3], ci[nt][3]);
            uint2 u1;
            u1.x = *reinterpret_cast<u32*>(&p10);
            u1.y = *reinterpret_cast<u32*>(&p11);
            *reinterpret_cast<uint2*>(Of + (b0+8)*64 + o) = u1;
        }
        if (g + 1 < ngates) {
            __syncthreads();
            const uint4* src = reinterpret_cast<const uint4*>(
                d_Wt[gb + g + 1] + (size_t)f * WFS);
            uint4* dst = reinterpret_cast<uint4*>(sW);
            #pragma unroll
            for (int i = tid; i < 1024; i += 128) dst[(i >> 3)*9 + (i & 7)] = src[i];
            __syncthreads();
        }
    }
}

// ---------------- inverse x-FFT (8-way DIT): d_F -> d_Ax ---------------------
__global__ void k_inv1(int pass) {
    pdl_wait();
    int k = blockIdx.x;
    int lane = threadIdx.x & 31;
    int wid  = threadIdx.x >> 5;
    int e = lane >> 2;
    int r = lane & 3;
    int bw = blockIdx.y * 32 + wid * 4 + r;
    const __half2* F = (pass == 0 && blockIdx.z == 1) ? d_F1 : d_F0;
    __half2* A = (pass == 1 || blockIdx.z == 1) ? d_Ax1 : d_Ax0;

    const bool hi1 = (e >= 4);
    const bool hi2 = (e & 2) != 0;
    const bool hi3 = (e & 1) != 0;
    const int ce = brevN(e, 3);
    const int b3 = e & 3;
    const float cb = (b3 == 0) ? 1.f : ((b3 == 1) ? 0.70710678f : ((b3 == 2) ? 0.f : -0.70710678f));
    const float sb = (b3 == 0) ? 0.f : ((b3 == 1) ? 0.70710678f : ((b3 == 2) ? 1.f :  0.70710678f));

    float ar[8], ai[8];
    #pragma unroll
    for (int m = 0; m < 8; m++) {
        float2 v = h2f(F[((size_t)(8*m + ce)*YHN + k)*BWN + bw]);
        ar[m] = v.x; ai[m] = v.y;
    }
    fftreg<1,3>(ar, ai);
    // stage 3' (xor4): combine 8->16, twiddle W64^{+4j}
    #pragma unroll
    for (int j = 0; j < 8; j++) {
        float br = __shfl_xor_sync(0xffffffffu, ar[j], 4);
        float bi = __shfl_xor_sync(0xffffffffu, ai[j], 4);
        const float c = twcos(4*j), s = twsin(4*j);
        if (!hi3) { ar[j] += br*c - bi*s;  ai[j] += br*s + bi*c; }
        else {
            float tr = ar[j]*c - ai[j]*s, ti = ar[j]*s + ai[j]*c;
            ar[j] = br - tr;  ai[j] = bi - ti;
        }
    }
    // stage 2' (xor8): combine 16->32, twiddle W64^{+16(e&1)+2j}
    #pragma unroll
    for (int j = 0; j < 8; j++) {
        float br = __shfl_xor_sync(0xffffffffu, ar[j], 8);
        float bi = __shfl_xor_sync(0xffffffffu, ai[j], 8);
        const float c2 = twcos(2*j), s2 = twsin(2*j);
        const float c = hi3 ? -s2 : c2;
        const float s = hi3 ?  c2 : s2;
        if (!hi2) { ar[j] += br*c - bi*s;  ai[j] += br*s + bi*c; }
        else {
            float tr = ar[j]*c - ai[j]*s, ti = ar[j]*s + ai[j]*c;
            ar[j] = br - tr;  ai[j] = bi - ti;
        }
    }
    // stage 1' (xor16): combine 32->64, twiddle W64^{+8(e&3)+j}
    #pragma unroll
    for (int j = 0; j < 8; j++) {
        float br = __shfl_xor_sync(0xffffffffu, ar[j], 16);
        float bi = __shfl_xor_sync(0xffffffffu, ai[j], 16);
        const float cj = twcos(j), sj = twsin(j);
        const float c = cb*cj - sb*sj;
        const float s = sb*cj + cb*sj;
        if (!hi1) { ar[j] += br*c - bi*s;  ai[j] += br*s + bi*c; }
        else {
            float tr = ar[j]*c - ai[j]*s, ti = ar[j]*s + ai[j]*c;
            ar[j] = br - tr;  ai[j] = bi - ti;
        }
    }
    pdl_trigger();
    // thread e holds x[8e + j] -> dense store (2 x uint4)
    uint4* dst = reinterpret_cast<uint4*>(A + ((size_t)bw*YHN + k)*64 + 8*e);
    #pragma unroll
    for (int j = 0; j < 2; j++) {
        __half2 h0 = __floats2half2_rn(ar[4*j+0], ai[4*j+0]);
        __half2 h1 = __floats2half2_rn(ar[4*j+1], ai[4*j+1]);
        __half2 h2 = __floats2half2_rn(ar[4*j+2], ai[4*j+2]);
        __half2 h3 = __floats2half2_rn(ar[4*j+3], ai[4*j+3]);
        uint4 u;
        u.x = *reinterpret_cast<u32*>(&h0);
        u.y = *reinterpret_cast<u32*>(&h1);
        u.z = *reinterpret_cast<u32*>(&h2);
        u.w = *reinterpret_cast<u32*>(&h3);
        dst[j] = u;
    }
}

// ---------------- fused: g = sigm(irfft(Ax1))*h, y-rfft(g) -------------------
__global__ void k_fused_zr() {
    pdl_wait();
    int bw = blockIdx.x;
    int lane = threadIdx.x & 31, wid = threadIdx.x >> 5;
    int t = wid*16 + (lane & 15);
    int hseg = lane >> 4;
    const float sc = 1.f / 2048.f;
    float zr[16], zi[16];
    irfft_build2(d_Ax1 + (size_t)bw * YHN * 64, t, hseg, zr, zi);
    const float4* hrow = reinterpret_cast<const float4*>(
        d_h + (size_t)bw * TILE + t*64 + 32*hseg);
    #pragma unroll
    for (int j = 0; j < 8; j++) {
        float4 h4 = hrow[j];
        zr[2*j]   = h4.x * sigm(zr[2*j]*sc);
        zi[2*j]   = h4.y * sigm(zi[2*j]*sc);
        zr[2*j+1] = h4.z * sigm(zr[2*j+1]*sc);
        zi[2*j+1] = h4.w * sigm(zi[2*j+1]*sc);
    }
    pdl_trigger();
    rfft_store2(d_A1 + (size_t)bw * YHN * 64, t, hseg, zr, zi);
}

// ---------------- fused: z = sigm(irfft(Ax0)), h += z(tanh(irfft(Ax1)) - h) --
__global__ void k_fused_h(int last) {
    pdl_wait();
    int bw = blockIdx.x;
    int lane = threadIdx.x & 31, wid = threadIdx.x >> 5;
    int t = wid*16 + (lane & 15);
    int hseg = lane >> 4;
    const float sc = 1.f / 2048.f;
    float zvr[16], zvi[16];
    irfft_build2(d_Ax0 + (size_t)bw * YHN * 64, t, hseg, zvr, zvi);
    #pragma unroll
    for (int j = 0; j < 16; j++) { zvr[j] = sigm(zvr[j]*sc); zvi[j] = sigm(zvi[j]*sc); }
    float nr[16], ni[16];
    irfft_build2(d_Ax1 + (size_t)bw * YHN * 64, t, hseg, nr, ni);
    pdl_trigger();
    float4* hrow = reinterpret_cast<float4*>(
        d_h + (size_t)bw * TILE + t*64 + 32*hseg);
    #pragma unroll
    for (int j = 0; j < 8; j++) {
        float4 h4 = hrow[j];
        float n0 = ftanh(nr[2*j]*sc),   n1 = ftanh(ni[2*j]*sc);
        float n2 = ftanh(nr[2*j+1]*sc), n3 = ftanh(ni[2*j+1]*sc);
        h4.x += zvr[2*j]   * (n0 - h4.x);
        h4.y += zvi[2*j]   * (n1 - h4.y);
        h4.z += zvr[2*j+1] * (n2 - h4.z);
        h4.w += zvi[2*j+1] * (n3 - h4.w);
        hrow[j] = h4;
        nr[2*j] = h4.x; ni[2*j] = h4.y; nr[2*j+1] = h4.z; ni[2*j+1] = h4.w;
    }
    if (!last)
        rfft_store2(d_A1 + (size_t)bw * YHN * 64, t, hseg, nr, ni);
}

// ---------------- out mapping: y = h @ Wo + bo (4-way w-split) ---------------
__global__ void k_out(const float* __restrict__ Wo, const float* __restrict__ bo,
                      float* __restrict__ out, int t) {
    __shared__ float sp[3*256];
    pdl_wait();
    int b = blockIdx.x;
    int xyl = threadIdx.x & 255;
    int xy = blockIdx.y * 256 + xyl;
    int wq = threadIdx.x >> 8;       // 0..3
    float acc = 0.f;
    const float* hb = d_h + (size_t)(b*64 + wq*16) * TILE + xy;
    #pragma unroll
    for (int w = 0; w < 16; w++)
        acc += hb[(size_t)w * TILE] * __ldg(&Wo[wq*16 + w]);
    if (wq > 0) sp[(wq-1)*256 + xyl] = acc;
    __syncthreads();
    pdl_trigger();   // `out` is not read by any dependent kernel
    if (wq == 0) {
        acc += sp[xyl] + sp[256 + xyl] + sp[512 + xyl] + bo[0];
        out[(size_t)(b*TT + t) * TILE + xy] = acc;
    }
}

// ---------------- PDL launch helper ------------------------------------------
template<typename... A, typename... B>
static inline void pdl_launch(void(*kern)(A...), dim3 grid, dim3 block, B... args) {
    cudaLaunchConfig_t cfg = {};
    cfg.gridDim = grid;
    cfg.blockDim = block;
    cfg.stream = 0;
    cudaLaunchAttribute at[1];
    at[0].id = cudaLaunchAttributeProgrammaticStreamSerialization;
    at[0].val.programmaticStreamSerializationAllowed = 1;
    cfg.attrs = at;
    cfg.numAttrs = 1;
    cudaLaunchKernelEx(&cfg, kern, (A)args...);
}

// ---------------- launch -----------------------------------------------------
extern "C" void kernel_launch(void* const* d_in, const int* in_sizes, int n_in,
                              void* d_out, int out_size) {
    int iX = 0, iWi = 2, iBi = 3, iWo = 4, iBo = 5, iWz = 6;
    if (n_in == 11) { iWi = 1; iBi = 2; iWo = 3; iBo = 4; iWz = 5; }

    const float* x    = (const float*)d_in[iX];
    const float* Wi   = (const float*)d_in[iWi];
    const float* bi   = (const float*)d_in[iBi];
    const float* Wo   = (const float*)d_in[iWo];
    const float* bo   = (const float*)d_in[iBo];
    float* out = (float*)d_out;

    k_wt_all<<<dim3(33, 64, 3), 256>>>((const float*)d_in[iWz+0], (const float*)d_in[iWz+1],
                                       (const float*)d_in[iWz+2], (const float*)d_in[iWz+3],
                                       (const float*)d_in[iWz+4], (const float*)d_in[iWz+5]);
    k_init_h<<<(BWN*TILE)/256, 256>>>(x, Wi, bi);
    k_fwd1<<<BWN, 64>>>();
    k_fwd2<<<dim3(YHN, 32), 256>>>();

    for (int t = 0; t < TT; t++) {
        pdl_launch(k_gemm, dim3(NF), dim3(128), 0);              // z->F0, r->F1
        pdl_launch(k_inv1, dim3(YHN, 32, 2), dim3(256), 0);      // F0->Ax0, F1->Ax1
        pdl_launch(k_fused_zr, dim3(BWN), dim3(128));            // g = r*h, y-rfft
        pdl_launch(k_fwd2, dim3(YHN, 32), dim3(256));            // x-FFT(g) -> Hf
        pdl_launch(k_gemm, dim3(NF), dim3(128), 1);              // nh -> F0
        pdl_launch(k_inv1, dim3(YHN, 32, 1), dim3(256), 1);      // F0 -> Ax1
        pdl_launch(k_fused_h, dim3(BWN), dim3(128), (int)(t == TT-1));
        if (t < TT-1) pdl_launch(k_fwd2, dim3(YHN, 32), dim3(256));
        pdl_launch(k_out, dim3(BB, TILE/256), dim3(1024), Wo, bo, out, t);
    }
}

// round 16
// speedup vs baseline: 1.1029x; 1.0780x over previous
#include <cuda_runtime.h>
#include <cuda_fp16.h>
#include <math.h>

#define BB   16
#define WWC  64
#define TT   20
#define YHN  33
#define NF   2112          // 64 * 33
#define BWN  1024          // BB * WWC
#define TILE 4096
#define LDH  72            // H smem row stride in halfs (144B, bank-rotating)
#define LDW  72            // W smem row stride in halfs
#define WFS  8192          // halfs per f per gate in GLOBAL (compact): 2*64*64

typedef unsigned int u32;

// ---------------- device scratch ------------------------------------------
static __device__ float  d_h [BWN*TILE];
static __device__ __align__(16) __half2 d_A1 [(size_t)BWN*YHN*64];   // [bw][k][x]
static __device__ __align__(16) __half2 d_Hf [(size_t)NF*BWN];       // [f][bw]
static __device__ __align__(16) __half2 d_F0 [(size_t)NF*BWN];
static __device__ __align__(16) __half2 d_F1 [(size_t)NF*BWN];
static __device__ __align__(16) __half2 d_Ax0[(size_t)BWN*YHN*64];   // [bw][k][x]
static __device__ __align__(16) __half2 d_Ax1[(size_t)BWN*YHN*64];
static __device__ __align__(16) __half  d_Wt [3][(size_t)NF*WFS];    // [f][p][w][o] compact

// ---------------- PDL helpers -------------------------------------------------
__device__ __forceinline__ void pdl_wait()    { asm volatile("griddepcontrol.wait;" ::: "memory"); }
__device__ __forceinline__ void pdl_trigger() { asm volatile("griddepcontrol.launch_dependents;" ::: "memory"); }

// ---------------- cp.async helpers --------------------------------------------
__device__ __forceinline__ void cp16(u32 dst, const void* src) {
    asm volatile("cp.async.cg.shared.global [%0], [%1], 16;" :: "r"(dst), "l"(src));
}
__device__ __forceinline__ void cp_commit() { asm volatile("cp.async.commit_group;"); }
template<int N> __device__ __forceinline__ void cp_wait() {
    asm volatile("cp.async.wait_group %0;" :: "n"(N));
}

// ---------------- mma / ldmatrix helpers -------------------------------------
__device__ __forceinline__ u32 smem_u32(const void* p) {
    return (u32)__cvta_generic_to_shared(p);
}
__device__ __forceinline__ void ldsm_x4(u32& r0, u32& r1, u32& r2,
                                        u32& r3, u32 addr) {
    asm volatile("ldmatrix.sync.aligned.m8n8.x4.shared.b16 {%0,%1,%2,%3},[%4];"
                 : "=r"(r0), "=r"(r1), "=r"(r2), "=r"(r3) : "r"(addr));
}
__device__ __forceinline__ void ldsm_x4t(u32& r0, u32& r1, u32& r2,
                                         u32& r3, u32 addr) {
    asm volatile("ldmatrix.sync.aligned.m8n8.x4.trans.shared.b16 {%0,%1,%2,%3},[%4];"
                 : "=r"(r0), "=r"(r1), "=r"(r2), "=r"(r3) : "r"(addr));
}
__device__ __forceinline__ void mma16816(float* c, const u32* a,
                                         u32 b0, u32 b1) {
    asm volatile(
        "mma.sync.aligned.m16n8k16.row.col.f32.f16.f16.f32 "
        "{%0,%1,%2,%3},{%4,%5,%6,%7},{%8,%9},{%0,%1,%2,%3};"
        : "+f"(c[0]), "+f"(c[1]), "+f"(c[2]), "+f"(c[3])
        : "r"(a[0]), "r"(a[1]), "r"(a[2]), "r"(a[3]), "r"(b0), "r"(b1));
}

// ---------------- compile-time twiddles (units of 2*pi/64) ------------------
__device__ __host__ constexpr float TWQ_(int i) {
    constexpr float q[17] = {
        1.000000000f, 0.995184727f, 0.980785280f, 0.956940336f,
        0.923879533f, 0.881921264f, 0.831469612f, 0.773010453f,
        0.707106781f, 0.634393284f, 0.555570233f, 0.471396737f,
        0.382683432f, 0.290284677f, 0.195090322f, 0.098017140f, 0.f };
    return q[i];
}
__device__ __host__ constexpr float twcos(int j) {
    j &= 63;
    if (j <= 16) return TWQ_(j);
    if (j <= 32) return -TWQ_(32 - j);
    if (j <= 48) return -TWQ_(j - 32);
    return TWQ_(64 - j);
}
__device__ __host__ constexpr float twsin(int j) { return twcos(j + 48); }
__device__ __host__ constexpr int brevN(int n, int bits) {
    int r = 0;
    for (int b = 0; b < bits; b++) r |= ((n >> b) & 1) << (bits - 1 - b);
    return r;
}

template<int SGN, int LOGN>
__device__ __forceinline__ void fftreg(float* xr, float* xi) {
    const int N = 1 << LOGN;
    #pragma unroll
    for (int n = 1; n < N; n++) {
        const int r = brevN(n, LOGN);
        if (r > n) {
            float a = xr[n]; xr[n] = xr[r]; xr[r] = a;
            float b = xi[n]; xi[n] = xi[r]; xi[r] = b;
        }
    }
    #pragma unroll
    for (int s = 0; s < LOGN; s++) {
        const int half = 1 << s;
        #pragma unroll
        for (int j = 0; j < N/2; j++) {
            const int k  = j & (half - 1);
            const int g  = j >> s;
            const int i1 = g * (half << 1) + k;
            const int i2 = i1 + half;
            const float wr = twcos(k << (5 - s));
            const float wi = (float)SGN * twsin(k << (5 - s));
            float vr = xr[i2], vi = xi[i2];
            float tr = vr * wr - vi * wi;
            float ti = vr * wi + vi * wr;
            float ur = xr[i1], ui = xi[i1];
            xr[i1] = ur + tr;  xi[i1] = ui + ti;
            xr[i2] = ur - tr;  xi[i2] = ui - ti;
        }
    }
}

__device__ __forceinline__ float sigm(float v) { return 1.f / (1.f + __expf(-v)); }
__device__ __forceinline__ float ftanh(float v) { return 2.f / (1.f + __expf(-2.f*v)) - 1.f; }
__device__ __forceinline__ float2 h2f(__half2 h) { return __half22float2(h); }

// ================= 2-way split packed real-FFT pipeline ======================
__device__ __forceinline__ void irfft_build2(const __half2* __restrict__ A,
                                             int t, int hseg, float* zr, float* zi) {
    if (!hseg) {
        float2 x0  = h2f(A[t]);
        float2 x32 = h2f(A[32*64 + t]);
        float2 x16 = h2f(A[16*64 + t]);
        zr[0] = 0.5f*(x0.x + x32.x);   zi[0] = 0.5f*(x0.x - x32.x);
        zr[8] = x16.x;                 zi[8] = -x16.y;
        #pragma unroll
        for (int k = 2; k <= 14; k += 2) {
            float2 a = h2f(A[k*64 + t]);
            float2 b = h2f(A[(32-k)*64 + t]);
            float Sr = 0.5f*(a.x + b.x), Si = 0.5f*(a.y - b.y);
            float Dr = 0.5f*(a.x - b.x), Di = 0.5f*(a.y + b.y);
            const float c = twcos(k), s = twsin(k);
            float XoR = c*Dr - s*Di;
            float XoI = c*Di + s*Dr;
            zr[k/2]    = Sr - XoI;  zi[k/2]    = Si + XoR;
            zr[16-k/2] = Sr + XoI;  zi[16-k/2] = XoR - Si;
        }
    } else {
        #pragma unroll
        for (int k = 1; k <= 15; k += 2) {
            float2 a = h2f(A[k*64 + t]);
            float2 b = h2f(A[(32-k)*64 + t]);
            float Sr = 0.5f*(a.x + b.x), Si = 0.5f*(a.y - b.y);
            float Dr = 0.5f*(a.x - b.x), Di = 0.5f*(a.y + b.y);
            const float c = twcos(k), s = twsin(k);
            float XoR = c*Dr - s*Di;
            float XoI = c*Di + s*Dr;
            zr[(k-1)/2]      = Sr - XoI;  zi[(k-1)/2]      = Si + XoR;
            zr[15-(k-1)/2]   = Sr + XoI;  zi[15-(k-1)/2]   = XoR - Si;
        }
    }
    fftreg<1,4>(zr, zi);
    #pragma unroll
    for (int j = 0; j < 16; j++) {
        float br = __shfl_xor_sync(0xffffffffu, zr[j], 16);
        float bi = __shfl_xor_sync(0xffffffffu, zi[j], 16);
        const float c = twcos(2*j), s = twsin(2*j);
        if (!hseg) { zr[j] += br*c - bi*s;  zi[j] += br*s + bi*c; }
        else {
            float tr = zr[j]*c - zi[j]*s, ti = zr[j]*s + zi[j]*c;
            zr[j] = br - tr;  zi[j] = bi - ti;
        }
    }
}

__device__ __forceinline__ void rfft_store2(__half2* __restrict__ out,
                                            int t, int hseg, float* zr, float* zi) {
    #pragma unroll
    for (int j = 0; j < 16; j++) {
        float br = __shfl_xor_sync(0xffffffffu, zr[j], 16);
        float bi = __shfl_xor_sync(0xffffffffu, zi[j], 16);
        if (!hseg) { zr[j] += br;  zi[j] += bi; }
        else {
            float dr = br - zr[j], di = bi - zi[j];
            const float c = twcos(2*j), s = twsin(2*j);
            zr[j] = dr*c + di*s;
            zi[j] = di*c - dr*s;
        }
    }
    fftreg<-1,4>(zr, zi);
    if (!hseg) {
        out[0*64 + t]  = __floats2half2_rn(zr[0] + zi[0], 0.f);
        out[32*64 + t] = __floats2half2_rn(zr[0] - zi[0], 0.f);
        out[16*64 + t] = __floats2half2_rn(zr[8], -zi[8]);
        #pragma unroll
        for (int k = 2; k <= 14; k += 2) {
            const int m = k/2, mq = 16 - k/2;
            float XeR = 0.5f*(zr[m] + zr[mq]), XeI = 0.5f*(zi[m] - zi[mq]);
            float XoR = 0.5f*(zi[m] + zi[mq]), XoI = 0.5f*(zr[mq] - zr[m]);
            const float c = twcos(k), s = twsin(k);
            float wXoR = c*XoR + s*XoI;
            float wXoI = c*XoI - s*XoR;
            out[k*64 + t]      = __floats2half2_rn(XeR + wXoR, XeI + wXoI);
            out[(32-k)*64 + t] = __floats2half2_rn(XeR - wXoR, -(XeI - wXoI));
        }
    } else {
        #pragma unroll
        for (int k = 1; k <= 15; k += 2) {
            const int m = (k-1)/2, mq = 15 - (k-1)/2;
            float XeR = 0.5f*(zr[m] + zr[mq]), XeI = 0.5f*(zi[m] - zi[mq]);
            float XoR = 0.5f*(zi[m] + zi[mq]), XoI = 0.5f*(zr[mq] - zr[m]);
            const float c = twcos(k), s = twsin(k);
            float wXoR = c*XoR + s*XoI;
            float wXoI = c*XoI - s*XoR;
            out[k*64 + t]      = __floats2half2_rn(XeR + wXoR, XeI + wXoI);
            out[(32-k)*64 + t] = __floats2half2_rn(XeR - wXoR, -(XeI - wXoI));
        }
    }
}

// ---- single-thread forward rfft (prologue only) ----------------------------
__device__ __forceinline__ void rfft_store1(__half2* __restrict__ out, int t,
                                            float* zr, float* zi) {
    fftreg<-1,5>(zr, zi);
    out[0*64 + t]  = __floats2half2_rn(zr[0] + zi[0], 0.f);
    out[32*64 + t] = __floats2half2_rn(zr[0] - zi[0], 0.f);
    out[16*64 + t] = __floats2half2_rn(zr[16], -zi[16]);
    #pragma unroll
    for (int k = 1; k < 16; k++) {
        const int q = 32 - k;
        float XeR = 0.5f*(zr[k] + zr[q]), XeI = 0.5f*(zi[k] - zi[q]);
        float XoR = 0.5f*(zi[k] + zi[q]), XoI = 0.5f*(zr[q] - zr[k]);
        const float c = twcos(k), s = twsin(k);
        float wXoR = c*XoR + s*XoI;
        float wXoI = c*XoI - s*XoR;
        out[k*64 + t] = __floats2half2_rn(XeR + wXoR, XeI + wXoI);
        out[q*64 + t] = __floats2half2_rn(XeR - wXoR, -(XeI - wXoI));
    }
}

// ---------------- weight transpose: [i][o][f] -> [f][p][w=i][o] compact fp16 -
__global__ void k_wt_all(const float* __restrict__ p0r, const float* __restrict__ p0i,
                         const float* __restrict__ p1r, const float* __restrict__ p1i,
                         const float* __restrict__ p2r, const float* __restrict__ p2i) {
    __shared__ float s_r[64*65];
    __shared__ float s_i[64*65];
    int gate = blockIdx.z;
    const float* wr = gate == 0 ? p0r : (gate == 1 ? p1r : p2r);
    const float* wi = gate == 0 ? p0i : (gate == 1 ? p1i : p2i);
    int f0  = blockIdx.x * 64;
    int io0 = blockIdx.y * 64;
    int lane = threadIdx.x & 63;
    int row  = threadIdx.x >> 6;
    #pragma unroll
    for (int r = row; r < 64; r += 4) {
        s_r[r*65 + lane] = wr[(size_t)(io0 + r) * NF + f0 + lane];
        s_i[r*65 + lane] = wi[(size_t)(io0 + r) * NF + f0 + lane];
    }
    __syncthreads();
    __half* out = d_Wt[gate];
    #pragma unroll
    for (int fl = row; fl < 64; fl += 4) {
        size_t base = (size_t)(f0 + fl) * WFS + (size_t)blockIdx.y * 64 + lane;
        out[base]        = __float2half_rn(s_r[lane*65 + fl]);
        out[base + 4096] = __float2half_rn(s_i[lane*65 + fl]);
    }
}

// ---------------- h0 = x @ Wi + bi (CIN=1) ----------------------------------
__global__ void k_init_h(const float* __restrict__ x, const float* __restrict__ Wi,
                         const float* __restrict__ bi) {
    int idx = blockIdx.x * 256 + threadIdx.x;
    int bw = idx >> 12;
    int xy = idx & 4095;
    int b = bw >> 6, w = bw & 63;
    d_h[idx] = x[b * TILE + xy] * Wi[w] + bi[w];
}

// ---------------- prologue: y-rfft of h (runs once) --------------------------
__global__ void k_fwd1() {
    int bw = blockIdx.x, t = threadIdx.x;
    const float4* row = reinterpret_cast<const float4*>(d_h + (size_t)bw * TILE + t*64);
    float zr[32], zi[32];
    #pragma unroll
    for (int j = 0; j < 16; j++) {
        float4 v = row[j];
        zr[2*j] = v.x; zi[2*j] = v.y; zr[2*j+1] = v.z; zi[2*j+1] = v.w;
    }
    rfft_store1(d_A1 + (size_t)bw * YHN * 64, t, zr, zi);
}

// ---------------- x-FFT (4-way DIF): d_A1[bw][k][x] -> d_Hf[f][bw] -----------
__global__ void k_fwd2() {
    pdl_wait();
    int k = blockIdx.x;
    int lane = threadIdx.x & 31;
    int wid  = threadIdx.x >> 5;
    int q = lane >> 3;
    int r = lane & 7;
    int bw = blockIdx.y * 32 + wid * 8 + r;
    bool qlo1 = (q < 2);
    bool qodd = (q & 1);

    float ar[16], ai[16];
    const uint4* src = reinterpret_cast<const uint4*>(
        d_A1 + ((size_t)bw*YHN + k)*64 + 16*q);
    #pragma unroll
    for (int j = 0; j < 4; j++) {
        uint4 v = src[j];
        float2 c0 = h2f(*reinterpret_cast<__half2*>(&v.x));
        float2 c1 = h2f(*reinterpret_cast<__half2*>(&v.y));
        float2 c2 = h2f(*reinterpret_cast<__half2*>(&v.z));
        float2 c3 = h2f(*reinterpret_cast<__half2*>(&v.w));
        ar[4*j+0] = c0.x; ai[4*j+0] = c0.y;
        ar[4*j+1] = c1.x; ai[4*j+1] = c1.y;
        ar[4*j+2] = c2.x; ai[4*j+2] = c2.y;
        ar[4*j+3] = c3.x; ai[4*j+3] = c3.y;
    }
    #pragma unroll
    for (int j = 0; j < 16; j++) {
        float br = __shfl_xor_sync(0xffffffffu, ar[j], 16);
        float bi = __shfl_xor_sync(0xffffffffu, ai[j], 16);
        if (qlo1) { ar[j] += br;  ai[j] += bi; }
        else {
            float dr = br - ar[j], di = bi - ai[j];
            const float cj = twcos(j), sj = twsin(j);
            float c = qodd ? -sj : cj;
            float s = qodd ?  cj : sj;
            ar[j] = dr*c + di*s;
            ai[j] = di*c - dr*s;
        }
    }
    #pragma unroll
    for (int j = 0; j < 16; j++) {
        float br = __shfl_xor_sync(0xffffffffu, ar[j], 8);
        float bi = __shfl_xor_sync(0xffffffffu, ai[j], 8);
        if (!qodd) { ar[j] += br;  ai[j] += bi; }
        else {
            float dr = br - ar[j], di = bi - ai[j];
            const float c = twcos(2*j), s = twsin(2*j);
            ar[j] = dr*c + di*s;
            ai[j] = di*c - dr*s;
        }
    }
    fftreg<-1,4>(ar, ai);
    pdl_trigger();
    int cq = ((q & 1) << 1) | (q >> 1);
    #pragma unroll
    for (int m = 0; m < 16; m++)
        d_Hf[((size_t)(4*m + cq)*YHN + k)*BWN + bw] = __floats2half2_rn(ar[m], ai[m]);
}

// ---------------- per-frequency complex GEMM via tensor cores ----------------
// cp.async weight prefetch: gate weights stream in BEFORE pdl_wait (overlapping
// the predecessor kernel); pass 0 double-buffers the two gates.
// Compact source per gate = 1024 uint4 (128 rows x 8); padded dst rows of 9.
template<int PASS>
__global__ void k_gemm() {
    const int f = blockIdx.x;
    __shared__ __align__(16) __half sHr[16*LDH];
    __shared__ __align__(16) __half sHi[16*LDH];
    __shared__ __align__(16) __half sW0[2*64*LDW];
    __shared__ __align__(16) __half sW1[(PASS == 0) ? 2*64*LDW : 8];
    const int tid = threadIdx.x;             // 128
    const int lane = tid & 31, wid = tid >> 5;
    const int gb = (PASS == 0) ? 0 : 2;
    const int ngates = (PASS == 0) ? 2 : 1;

    // ---- pre-wait weight prefetch (overlaps predecessor execution) ----
    {
        u32 d0 = smem_u32(sW0);
        const __half* g0 = d_Wt[gb] + (size_t)f * WFS;
        #pragma unroll
        for (int i = tid; i < 1024; i += 128)
            cp16(d0 + (u32)(((i >> 3)*9 + (i & 7))*16), g0 + (size_t)i*8);
        cp_commit();
        if (PASS == 0) {
            u32 d1 = smem_u32(sW1);
            const __half* g1 = d_Wt[1] + (size_t)f * WFS;
            #pragma unroll
            for (int i = tid; i < 1024; i += 128)
                cp16(d1 + (u32)(((i >> 3)*9 + (i & 7))*16), g1 + (size_t)i*8);
            cp_commit();
        }
    }
    pdl_wait();
    {
        const __half2* Hsrc = d_Hf + (size_t)f * BWN;
        #pragma unroll
        for (int i = tid; i < BWN; i += 128) {
            __half2 v = Hsrc[i];
            int b = i >> 6, w = i & 63;
            sHr[b*LDH + w] = __low2half(v);
            sHi[b*LDH + w] = __high2half(v);
        }
    }
    cp_wait<(PASS == 0) ? 1 : 0>();
    __syncthreads();

    const int obase = wid * 16;
    const u32 baseHr = smem_u32(sHr);
    const u32 baseHi = smem_u32(sHi);
    const int arow = lane & 15, acol = (lane >> 4) * 8;

    for (int g = 0; g < ngates; g++) {
        if (g == 1) { cp_wait<0>(); __syncthreads(); }
        const u32 baseW = (g == 0) ? smem_u32(sW0) : smem_u32(sW1);
        __half2* O = (PASS == 0 && g == 1) ? d_F1 : d_F0;

        float cr[2][4] = {{0.f,0.f,0.f,0.f},{0.f,0.f,0.f,0.f}};
        float ci[2][4] = {{0.f,0.f,0.f,0.f},{0.f,0.f,0.f,0.f}};

        #pragma unroll
        for (int kk = 0; kk < 4; kk++) {
            u32 Ar[4], Ai[4], An[4];
            u32 aoff = (u32)((arow*LDH + kk*16 + acol) * 2);
            ldsm_x4(Ar[0], Ar[1], Ar[2], Ar[3], baseHr + aoff);
            ldsm_x4(Ai[0], Ai[1], Ai[2], Ai[3], baseHi + aoff);
            #pragma unroll
            for (int j = 0; j < 4; j++) An[j] = Ai[j] ^ 0x80008000u;

            u32 Br[4], Bi[4];
            u32 boff = (u32)(((kk*16 + (lane & 15))*LDW
                              + obase + (lane >> 4)*8) * 2);
            ldsm_x4t(Br[0], Br[1], Br[2], Br[3], baseW + boff);
            ldsm_x4t(Bi[0], Bi[1], Bi[2], Bi[3], baseW + (u32)(64*LDW*2) + boff);

            #pragma unroll
            for (int nt = 0; nt < 2; nt++) {
                mma16816(cr[nt], Ar, Br[2*nt], Br[2*nt+1]);
                mma16816(cr[nt], An, Bi[2*nt], Bi[2*nt+1]);
                mma16816(ci[nt], Ar, Bi[2*nt], Bi[2*nt+1]);
                mma16816(ci[nt], Ai, Br[2*nt], Br[2*nt+1]);
            }
        }

        if (g == ngates - 1) pdl_trigger();
        __half2* Of = O + (size_t)f * BWN;
        int b0 = lane >> 2, oc = (lane & 3) * 2;
        #pragma unroll
        for (int nt = 0; nt < 2; nt++) {
            int o = obase + nt*8 + oc;
            __half2 p00 = __floats2half2_rn(cr[nt][0], ci[nt][0]);
            __half2 p01 = __floats2half2_rn(cr[nt][1], ci[nt][1]);
            uint2 u0;
            u0.x = *reinterpret_cast<u32*>(&p00);
            u0.y = *reinterpret_cast<u32*>(&p01);
            *reinterpret_cast<uint2*>(Of + b0*64 + o) = u0;
            __half2 p10 = __floats2half2_rn(cr[nt][2], ci[nt][2]);
            __half2 p11 = __floats2half2_rn(cr[nt][3], ci[nt][3]);
            uint2 u1;
            u1.x = *reinterpret_cast<u32*>(&p10);
            u1.y = *reinterpret_cast<u32*>(&p11);
            *reinterpret_cast<uint2*>(Of + (b0+8)*64 + o) = u1;
        }
    }
}

// ---------------- inverse x-FFT (4-way DIT): d_F -> d_Ax ---------------------
__global__ void k_inv1(int pass) {
    pdl_wait();
    int k = blockIdx.x;
    int lane = threadIdx.x & 31;
    int wid  = threadIdx.x >> 5;
    int q = lane >> 3;
    int r = lane & 7;
    int bw = blockIdx.y * 32 + wid * 8 + r;
    bool qlo1 = (q < 2);
    bool qodd = (q & 1);
    const __half2* F = (pass == 0 && blockIdx.z == 1) ? d_F1 : d_F0;
    __half2* A = (pass == 1 || blockIdx.z == 1) ? d_Ax1 : d_Ax0;

    int cq = ((q & 1) << 1) | (q >> 1);
    float ar[16], ai[16];
    #pragma unroll
    for (int m = 0; m < 16; m++) {
        float2 v = h2f(F[((size_t)(4*m + cq)*YHN + k)*BWN + bw]);
        ar[m] = v.x; ai[m] = v.y;
    }
    fftreg<1,4>(ar, ai);
    #pragma unroll
    for (int j = 0; j < 16; j++) {
        float br = __shfl_xor_sync(0xffffffffu, ar[j], 8);
        float bi = __shfl_xor_sync(0xffffffffu, ai[j], 8);
        const float c = twcos(2*j), s = twsin(2*j);
        if (!qodd) { ar[j] += br*c - bi*s;  ai[j] += br*s + bi*c; }
        else {
            float tr = ar[j]*c - ai[j]*s, ti = ar[j]*s + ai[j]*c;
            ar[j] = br - tr;  ai[j] = bi - ti;
        }
    }
    #pragma unroll
    for (int j = 0; j < 16; j++) {
        float br = __shfl_xor_sync(0xffffffffu, ar[j], 16);
        float bi = __shfl_xor_sync(0xffffffffu, ai[j], 16);
        const float cj = twcos(j), sj = twsin(j);
        float c = qodd ? -sj : cj;
        float s = qodd ?  cj : sj;
        if (qlo1) { ar[j] += br*c - bi*s;  ai[j] += br*s + bi*c; }
        else {
            float tr = ar[j]*c - ai[j]*s, ti = ar[j]*s + ai[j]*c;
            ar[j] = br - tr;  ai[j] = bi - ti;
        }
    }
    pdl_trigger();
    uint2* dst = reinterpret_cast<uint2*>(A + ((size_t)bw*YHN + k)*64 + 16*q);
    #pragma unroll
    for (int j = 0; j < 8; j++) {
        __half2 h0 = __floats2half2_rn(ar[2*j],   ai[2*j]);
        __half2 h1 = __floats2half2_rn(ar[2*j+1], ai[2*j+1]);
        uint2 u;
        u.x = *reinterpret_cast<u32*>(&h0);
        u.y = *reinterpret_cast<u32*>(&h1);
        dst[j] = u;
    }
}

// ---------------- fused: g = sigm(irfft(Ax1))*h, y-rfft(g) -------------------
__global__ void k_fused_zr() {
    pdl_wait();
    int bw = blockIdx.x;
    int lane = threadIdx.x & 31, wid = threadIdx.x >> 5;
    int t = wid*16 + (lane & 15);
    int hseg = lane >> 4;
    const float sc = 1.f / 2048.f;
    float zr[16], zi[16];
    irfft_build2(d_Ax1 + (size_t)bw * YHN * 64, t, hseg, zr, zi);
    const float4* hrow = reinterpret_cast<const float4*>(
        d_h + (size_t)bw * TILE + t*64 + 32*hseg);
    #pragma unroll
    for (int j = 0; j < 8; j++) {
        float4 h4 = hrow[j];
        zr[2*j]   = h4.x * sigm(zr[2*j]*sc);
        zi[2*j]   = h4.y * sigm(zi[2*j]*sc);
        zr[2*j+1] = h4.z * sigm(zr[2*j+1]*sc);
        zi[2*j+1] = h4.w * sigm(zi[2*j+1]*sc);
    }
    pdl_trigger();
    rfft_store2(d_A1 + (size_t)bw * YHN * 64, t, hseg, zr, zi);
}

// ---------------- fused: z = sigm(irfft(Ax0)), h += z(tanh(irfft(Ax1)) - h) --
__global__ void k_fused_h(int last) {
    pdl_wait();
    int bw = blockIdx.x;
    int lane = threadIdx.x & 31, wid = threadIdx.x >> 5;
    int t = wid*16 + (lane & 15);
    int hseg = lane >> 4;
    const float sc = 1.f / 2048.f;
    float zvr[16], zvi[16];
    irfft_build2(d_Ax0 + (size_t)bw * YHN * 64, t, hseg, zvr, zvi);
    #pragma unroll
    for (int j = 0; j < 16; j++) { zvr[j] = sigm(zvr[j]*sc); zvi[j] = sigm(zvi[j]*sc); }
    float nr[16], ni[16];
    irfft_build2(d_Ax1 + (size_t)bw * YHN * 64, t, hseg, nr, ni);
    pdl_trigger();
    float4* hrow = reinterpret_cast<float4*>(
        d_h + (size_t)bw * TILE + t*64 + 32*hseg);
    #pragma unroll
    for (int j = 0; j < 8; j++) {
        float4 h4 = hrow[j];
        float n0 = ftanh(nr[2*j]*sc),   n1 = ftanh(ni[2*j]*sc);
        float n2 = ftanh(nr[2*j+1]*sc), n3 = ftanh(ni[2*j+1]*sc);
        h4.x += zvr[2*j]   * (n0 - h4.x);
        h4.y += zvi[2*j]   * (n1 - h4.y);
        h4.z += zvr[2*j+1] * (n2 - h4.z);
        h4.w += zvi[2*j+1] * (n3 - h4.w);
        hrow[j] = h4;
        nr[2*j] = h4.x; ni[2*j] = h4.y; nr[2*j+1] = h4.z; ni[2*j+1] = h4.w;
    }
    if (!last)
        rfft_store2(d_A1 + (size_t)bw * YHN * 64, t, hseg, nr, ni);
}

// ---------------- out mapping: y = h @ Wo + bo (4-way w-split) ---------------
__global__ void k_out(const float* __restrict__ Wo, const float* __restrict__ bo,
                      float* __restrict__ out, int t) {
    __shared__ float sp[3*256];
    pdl_wait();
    int b = blockIdx.x;
    int xyl = threadIdx.x & 255;
    int xy = blockIdx.y * 256 + xyl;
    int wq = threadIdx.x >> 8;       // 0..3
    float acc = 0.f;
    const float* hb = d_h + (size_t)(b*64 + wq*16) * TILE + xy;
    #pragma unroll
    for (int w = 0; w < 16; w++)
        acc += hb[(size_t)w * TILE] * __ldg(&Wo[wq*16 + w]);
    if (wq > 0) sp[(wq-1)*256 + xyl] = acc;
    __syncthreads();
    pdl_trigger();   // `out` is not read by any dependent kernel
    if (wq == 0) {
        acc += sp[xyl] + sp[256 + xyl] + sp[512 + xyl] + bo[0];
        out[(size_t)(b*TT + t) * TILE + xy] = acc;
    }
}

// ---------------- PDL launch helper ------------------------------------------
template<typename... A, typename... B>
static inline void pdl_launch(void(*kern)(A...), dim3 grid, dim3 block, B... args) {
    cudaLaunchConfig_t cfg = {};
    cfg.gridDim = grid;
    cfg.blockDim = block;
    cfg.stream = 0;
    cudaLaunchAttribute at[1];
    at[0].id = cudaLaunchAttributeProgrammaticStreamSerialization;
    at[0].val.programmaticStreamSerializationAllowed = 1;
    cfg.attrs = at;
    cfg.numAttrs = 1;
    cudaLaunchKernelEx(&cfg, kern, (A)args...);
}

// ---------------- launch -----------------------------------------------------
extern "C" void kernel_launch(void* const* d_in, const int* in_sizes, int n_in,
                              void* d_out, int out_size) {
    int iX = 0, iWi = 2, iBi = 3, iWo = 4, iBo = 5, iWz = 6;
    if (n_in == 11) { iWi = 1; iBi = 2; iWo = 3; iBo = 4; iWz = 5; }

    const float* x    = (const float*)d_in[iX];
    const float* Wi   = (const float*)d_in[iWi];
    const float* bi   = (const float*)d_in[iBi];
    const float* Wo   = (const float*)d_in[iWo];
    const float* bo   = (const float*)d_in[iBo];
    float* out = (float*)d_out;

    k_wt_all<<<dim3(33, 64, 3), 256>>>((const float*)d_in[iWz+0], (const float*)d_in[iWz+1],
                                       (const float*)d_in[iWz+2], (const float*)d_in[iWz+3],
                                       (const float*)d_in[iWz+4], (const float*)d_in[iWz+5]);
    k_init_h<<<(BWN*TILE)/256, 256>>>(x, Wi, bi);
    k_fwd1<<<BWN, 64>>>();
    k_fwd2<<<dim3(YHN, 32), 128>>>();

    for (int t = 0; t < TT; t++) {
        pdl_launch(k_gemm<0>, dim3(NF), dim3(128));              // z->F0, r->F1
        pdl_launch(k_inv1, dim3(YHN, 32, 2), dim3(128), 0);      // F0->Ax0, F1->Ax1
        pdl_launch(k_fused_zr, dim3(BWN), dim3(128));            // g = r*h, y-rfft
        pdl_launch(k_fwd2, dim3(YHN, 32), dim3(128));            // x-FFT(g) -> Hf
        pdl_launch(k_gemm<1>, dim3(NF), dim3(128));              // nh -> F0
        pdl_launch(k_inv1, dim3(YHN, 32, 1), dim3(128), 1);      // F0 -> Ax1
        pdl_launch(k_fused_h, dim3(BWN), dim3(128), (int)(t == TT-1));
        if (t < TT-1) pdl_launch(k_fwd2, dim3(YHN, 32), dim3(128));
        pdl_launch(k_out, dim3(BB, TILE/256), dim3(1024), Wo, bo, out, t);
    }
}